// round 13
// baseline (speedup 1.0000x reference)
#include <cuda_runtime.h>
#include <cuda_fp16.h>
#include <cstdint>

#define Bn 4
#define Nn 256
#define Cc 32
#define Mm 4
#define OUTn 64

// ---------------- scratch (device globals: no allocation allowed) ----------------
__device__ float g_S1[Bn*Nn*Cc];      // rowsum  (mean over axis1)
__device__ float g_S2[Bn*Nn*Cc];      // colsum  (mean over axis2)
__device__ float g_D [Bn*Nn*Cc];      // diag
__device__ float g_p [Bn*Nn*Mm];      // sigmoid neighborhood
__device__ float g_U [Bn*Nn*Mm*Cc];
__device__ float g_V [Bn*Nn*Mm*Cc];
__device__ float g_part1[Bn*16*128];  // rcs2 partials
__device__ float g_part2[Bn*16*128];  // ds2  partials
__device__ float g_add[Bn*Nn*OUTn];
__device__ __half g_Wt[OUTn*2*Mm*Cc]; // w2d transposed: Wt[o][k]

// ---------------- sweep 1: rowpass (S2, D) + colpass (S1) + w2d->half ----------------
__global__ void k_sweep1(const float* __restrict__ x, const float* __restrict__ w2d){
    int blk = blockIdx.x;
    int tid = threadIdx.x;
    if (blk >= 2*Bn*Nn){
        int idx = (blk - 2*Bn*Nn) * 256 + tid;   // 16384
        int o = idx >> 8, k = idx & 255;
        g_Wt[idx] = __float2half(w2d[k*OUTn + o]);
        return;
    }
    __shared__ float red[8][32];
    int c = tid & 31, g = tid >> 5;
    if (blk < Bn*Nn){
        int bt = blk;
        int t = bt & (Nn-1);
        const float* xrow = x + (size_t)bt * Nn * Cc;
        float s = 0.f;
        #pragma unroll 8
        for (int j = g; j < Nn; j += 8) s += xrow[j*Cc + c];
        red[g][c] = s;
        __syncthreads();
        if (g == 0){
            float tot = 0.f;
            #pragma unroll
            for (int k = 0; k < 8; k++) tot += red[k][c];
            g_S2[bt*Cc + c] = tot * (1.0f/Nn);
            g_D [bt*Cc + c] = xrow[t*Cc + c];
        }
    } else {
        int bt = blk - Bn*Nn;
        int b = bt >> 8, t = bt & (Nn-1);
        const float* xb = x + (size_t)b*Nn*Nn*Cc + (size_t)t*Cc;
        float s = 0.f;
        #pragma unroll 8
        for (int i = g; i < Nn; i += 8) s += xb[(size_t)i*Nn*Cc + c];
        red[g][c] = s;
        __syncthreads();
        if (g == 0){
            float tot = 0.f;
            #pragma unroll
            for (int k = 0; k < 8; k++) tot += red[k][c];
            g_S1[bt*Cc + c] = tot * (1.0f/Nn);
        }
    }
}

// ---------------- neighborhood sigmoid: p[b,t,m], 1024 threads ----------------
__global__ __launch_bounds__(1024) void k_neighb(const float* __restrict__ w1, const float* __restrict__ b1,
                         const float* __restrict__ w0, const float* __restrict__ b0){
    int b = blockIdx.x;
    __shared__ float w1s[3*Cc*Mm];
    __shared__ float w0s[2*Cc*Mm];
    __shared__ float rcs[Cc], ds[Cc], z0[Mm];
    __shared__ float r1[32][32], r2[32][32];
    int tid = threadIdx.x;
    if (tid < 3*Cc*Mm) w1s[tid] = w1[tid];
    if (tid < 2*Cc*Mm) w0s[tid] = w0[tid];
    int c = tid & 31, g = tid >> 5;
    float s1 = 0.f, s2 = 0.f;
    #pragma unroll
    for (int t = g; t < Nn; t += 32){
        s1 += g_S1[(b*Nn + t)*Cc + c];
        s2 += g_D [(b*Nn + t)*Cc + c];
    }
    r1[g][c] = s1; r2[g][c] = s2;
    __syncthreads();
    if (tid < 32){
        float a = 0.f, d = 0.f;
        #pragma unroll
        for (int k = 0; k < 32; k++){ a += r1[k][c]; d += r2[k][c]; }
        rcs[c] = a * (1.0f/Nn);
        ds[c]  = d * (1.0f/Nn);
    }
    __syncthreads();
    if (tid < Mm){
        int m = tid;
        float z = b0[m];
        #pragma unroll
        for (int cc = 0; cc < Cc; cc++)
            z += rcs[cc]*w0s[cc*Mm + m] + ds[cc]*w0s[(Cc+cc)*Mm + m];
        z0[m] = z;
    }
    __syncthreads();
    int t = tid >> 2, m = tid & 3;
    const float* S1r = &g_S1[(b*Nn + t)*Cc];
    const float* S2r = &g_S2[(b*Nn + t)*Cc];
    const float* Dr  = &g_D [(b*Nn + t)*Cc];
    float node = b1[m] + z0[m];
    #pragma unroll
    for (int cc = 0; cc < Cc; cc++)
        node += S1r[cc]*w1s[cc*Mm+m] + S2r[cc]*w1s[(Cc+cc)*Mm+m] + Dr[cc]*w1s[(2*Cc+cc)*Mm+m];
    g_p[(b*Nn + t)*Mm + m] = 1.0f / (1.0f + expf(-node));
}

// ---------------- sweep 2: p-weighted contractions (V and U) ----------------
__global__ void k_sweep2(const float* __restrict__ x){
    int blk = blockIdx.x;
    bool is_v = blk < Bn*Nn;
    int bt = is_v ? blk : blk - Bn*Nn;
    int b = bt >> 8, t = bt & (Nn-1);
    const float* base;
    size_t stride;
    if (is_v){ base = x + (size_t)bt * Nn * Cc;              stride = Cc; }
    else     { base = x + (size_t)b*Nn*Nn*Cc + (size_t)t*Cc; stride = (size_t)Nn*Cc; }
    __shared__ float pv[Nn*Mm];
    __shared__ float red[8*Mm*32];
    int tid = threadIdx.x;
    ((float4*)pv)[tid] = ((const float4*)g_p)[b*Nn + tid];
    __syncthreads();
    int c = tid & 31, g = tid >> 5;
    float acc[Mm] = {0.f,0.f,0.f,0.f};
    #pragma unroll 8
    for (int j = g; j < Nn; j += 8){
        float v = base[(size_t)j*stride + c];
        #pragma unroll
        for (int m = 0; m < Mm; m++) acc[m] += v * pv[j*Mm + m];
    }
    #pragma unroll
    for (int m = 0; m < Mm; m++) red[(g*Mm + m)*32 + c] = acc[m];
    __syncthreads();
    if (g < Mm){
        int m = g;
        float s = 0.f;
        #pragma unroll
        for (int k = 0; k < 8; k++) s += red[(k*Mm + m)*32 + c];
        float* dst = is_v ? g_V : g_U;
        dst[(bt*Mm + m)*Cc + c] = s * (1.0f/Nn);
    }
}

// ---------------- rcs2/ds2 partials: grid = Bn*16, 8 t per thread ----------------
__global__ void k_rcs2p(){
    int blk = blockIdx.x;
    int b = blk >> 4, slice = blk & 15;
    __shared__ float pr1[256], pr2[256];
    int tid = threadIdx.x;
    int mc = tid & 127, sub = tid >> 7;
    int m = mc >> 5, c = mc & 31;
    float s1 = 0.f, s2 = 0.f;
    int t0 = slice*16 + sub*8;
    #pragma unroll
    for (int t = t0; t < t0+8; t++){
        float pvv = g_p[(b*Nn + t)*Mm + m];
        s1 += pvv * g_V[((b*Nn + t)*Mm + m)*Cc + c];
        s2 += pvv * pvv * g_D[(b*Nn + t)*Cc + c];
    }
    pr1[tid] = s1; pr2[tid] = s2;
    __syncthreads();
    if (tid < 128){
        g_part1[(b*16 + slice)*128 + tid] = pr1[tid] + pr1[tid+128];
        g_part2[(b*16 + slice)*128 + tid] = pr2[tid] + pr2[tid+128];
    }
}

// ---------------- add[b,t,o]: 256 blocks, 4 t per block ----------------
#define ADD_SMEM (4*384*4 + 96*64*4)
__global__ void k_add(const float* __restrict__ w1d, const float* __restrict__ w0d,
                      const float* __restrict__ b0d, const float* __restrict__ b1d,
                      const float* __restrict__ b2d){
    extern __shared__ float ash[];
    float* o1  = ash;
    float* wsh = ash + 4*384;
    __shared__ float rsh[128], dsh[128], zred[256], z0sh[64];
    int b = blockIdx.x >> 6;
    int t0 = (blockIdx.x & 63) * 4;
    int tid = threadIdx.x;

    #pragma unroll
    for (int it = 0; it < 6; it++){
        int idx = tid + it*256;
        int tl = idx / 384, k = idx - tl*384;
        int t = t0 + tl;
        int seg = k >> 7, mc = k & 127;
        int m = mc >> 5, c = mc & 31;
        float pv = g_p[(b*Nn + t)*Mm + m];
        float val;
        if (seg == 0)      val = pv * g_U[((b*Nn + t)*Mm + m)*Cc + c];
        else if (seg == 1) val = pv * g_V[((b*Nn + t)*Mm + m)*Cc + c];
        else               val = pv * pv * g_D[(b*Nn + t)*Cc + c];
        o1[idx] = val;
    }
    if (tid < 128){
        float a = 0.f, d = 0.f;
        #pragma unroll
        for (int s = 0; s < 16; s++){
            a += g_part1[(b*16 + s)*128 + tid];
            d += g_part2[(b*16 + s)*128 + tid];
        }
        rsh[tid] = a * (1.0f/Nn);
        dsh[tid] = d * (1.0f/Nn);
    }
    __syncthreads();
    {
        int o = tid & 63, q = tid >> 6;
        float s = 0.f;
        int k0 = q*32;
        #pragma unroll
        for (int k = k0; k < k0+32; k++)
            s += rsh[k]*w0d[k*OUTn + o] + dsh[k]*w0d[(128+k)*OUTn + o];
        zred[tid] = s;
    }
    __syncthreads();
    if (tid < 64)
        z0sh[tid] = zred[tid] + zred[tid+64] + zred[tid+128] + zred[tid+192]
                  + b0d[tid] + b1d[tid] + b2d[tid];

    int tq = tid >> 6, o = tid & 63;
    float acc = 0.f;
    #pragma unroll
    for (int chunk = 0; chunk < 4; chunk++){
        __syncthreads();
        {
            const float4* w4 = (const float4*)(w1d + chunk*96*64);
            #pragma unroll
            for (int it = 0; it < 6; it++)
                ((float4*)wsh)[tid + it*256] = w4[tid + it*256];
        }
        __syncthreads();
        #pragma unroll 8
        for (int k = 0; k < 96; k++)
            acc += o1[tq*384 + chunk*96 + k] * wsh[k*64 + o];
    }
    g_add[(b*Nn + t0 + tq)*OUTn + o] = acc + z0sh[o];
}

// ---------------- main fused GEMM: JPB 4, ldmatrix fragment loads ----------------
__device__ __forceinline__ void mma16816(float* c, const uint32_t* a, uint32_t b0, uint32_t b1){
    asm volatile("mma.sync.aligned.m16n8k16.row.col.f32.f16.f16.f32 "
        "{%0,%1,%2,%3}, {%4,%5,%6,%7}, {%8,%9}, {%0,%1,%2,%3};\n"
        : "+f"(c[0]), "+f"(c[1]), "+f"(c[2]), "+f"(c[3])
        : "r"(a[0]), "r"(a[1]), "r"(a[2]), "r"(a[3]), "r"(b0), "r"(b1));
}
__device__ __forceinline__ void ldsm_x4(uint32_t& r0, uint32_t& r1, uint32_t& r2, uint32_t& r3, uint32_t addr){
    asm volatile("ldmatrix.sync.aligned.m8n8.x4.shared.b16 {%0,%1,%2,%3}, [%4];"
        : "=r"(r0), "=r"(r1), "=r"(r2), "=r"(r3) : "r"(addr));
}
__device__ __forceinline__ uint32_t smem_u32(const void* p){
    uint32_t a;
    asm("{ .reg .u64 t; cvta.to.shared.u64 t, %1; cvt.u32.u64 %0, t; }" : "=r"(a) : "l"(p));
    return a;
}

#define AS 264   // padded row stride (halves)
#define ASB (AS*2)
#define SMEM_MAIN (128*AS*2 + 64*AS*2 + 512*4 + 64*4)
#define JPB 4    // grid = 512 blocks

__global__ __launch_bounds__(256, 2) void k_main(const float* __restrict__ x, float* __restrict__ out){
    extern __shared__ __align__(16) char smem[];
    __half* Ash  = (__half*)smem;                 // [128][AS]
    __half* Wsh  = Ash + 128*AS;                  // [64][AS]
    float*  sshf = (float*)(Wsh + 64*AS);         // [128][4] pi factors
    float*  addsh = sshf + 512;                   // [64]

    int blk = blockIdx.x;
    int ib = blk & 1, jp = (blk >> 1) & 63, b = blk >> 7;
    int i0 = ib * 128;
    int tid = threadIdx.x;

    // W tile: 2048 uint4, once per block
    {
        const uint4* Wt4 = (const uint4*)g_Wt;
        #pragma unroll
        for (int it = 0; it < 8; it++){
            int idx = tid + it*256;
            int o = idx >> 5, kq = idx & 31;
            *(uint4*)&Wsh[o*AS + kq*8] = Wt4[idx];
        }
    }
    if (tid < 128)
        ((float4*)sshf)[tid] = ((const float4*)g_p)[b*Nn + i0 + tid];
    __syncthreads();

    int lane = tid & 31, wid = tid >> 5;
    int wr = wid >> 1, wc = wid & 1;
    int gid = lane >> 2, tg = lane & 3;

    // ldmatrix address bases (byte smem addresses)
    uint32_t ash_u = smem_u32(Ash);
    uint32_t wsh_u = smem_u32(Wsh);
    int lrow = lane & 15, lsel = lane >> 4;       // 16-row index, k-half select
    uint32_t aAddr0 = ash_u + (uint32_t)(wr*32 + lrow)*ASB + (uint32_t)lsel*16;
    uint32_t bAddr0 = wsh_u + (uint32_t)(wc*32 + lrow)*ASB + (uint32_t)lsel*16;

    // register prefetch: column tile
    float2 vc[8];
    float4 pjv;
    float  addv;
    {
        int j = jp*JPB;
        size_t base_c = (((size_t)(b*Nn) + i0)*Nn + j)*Cc;
        #pragma unroll
        for (int it = 0; it < 8; it++){
            int idx = tid + it*256;
            int i = idx >> 4, cp = idx & 15;
            vc[it] = *(const float2*)(x + base_c + (size_t)i*(Nn*Cc) + cp*2);
        }
        pjv  = ((const float4*)g_p)[b*Nn + j];
        addv = g_add[(b*Nn + j)*OUTn + (tid & 63)];
    }

    for (int jj = 0; jj < JPB; jj++){
        int j = jp*JPB + jj;
        if (jj > 0) __syncthreads();

        // A build
        {
            size_t base_r = (((size_t)(b*Nn) + j)*Nn + i0)*Cc;
            #pragma unroll
            for (int it = 0; it < 8; it++){
                int idx = tid + it*256;
                int i = idx >> 4, cp = idx & 15;
                float4 pi = ((const float4*)sshf)[i];
                float4 s = make_float4(pi.x*pjv.x, pi.y*pjv.y, pi.z*pjv.z, pi.w*pjv.w);
                float2 v = vc[it];
                __half* arow = Ash + i*AS + cp*2;
                *(half2*)(arow     ) = __floats2half2_rn(s.x*v.x, s.x*v.y);
                *(half2*)(arow + 32) = __floats2half2_rn(s.y*v.x, s.y*v.y);
                *(half2*)(arow + 64) = __floats2half2_rn(s.z*v.x, s.z*v.y);
                *(half2*)(arow + 96) = __floats2half2_rn(s.w*v.x, s.w*v.y);
                float2 w = *(const float2*)(x + base_r + (size_t)i*Cc + cp*2);
                __half* brow = arow + 128;
                *(half2*)(brow     ) = __floats2half2_rn(s.x*w.x, s.x*w.y);
                *(half2*)(brow + 32) = __floats2half2_rn(s.y*w.x, s.y*w.y);
                *(half2*)(brow + 64) = __floats2half2_rn(s.z*w.x, s.z*w.y);
                *(half2*)(brow + 96) = __floats2half2_rn(s.w*w.x, s.w*w.y);
            }
            if (tid < 64) addsh[tid] = addv;
        }
        __syncthreads();

        // prefetch next j's column tile while MMA runs
        if (jj + 1 < JPB){
            int j2 = j + 1;
            size_t base_c = (((size_t)(b*Nn) + i0)*Nn + j2)*Cc;
            #pragma unroll
            for (int it = 0; it < 8; it++){
                int idx = tid + it*256;
                int i = idx >> 4, cp = idx & 15;
                vc[it] = *(const float2*)(x + base_c + (size_t)i*(Nn*Cc) + cp*2);
            }
            pjv  = ((const float4*)g_p)[b*Nn + j2];
            addv = g_add[(b*Nn + j2)*OUTn + (tid & 63)];
        }

        float acc[2][4][4];
        #pragma unroll
        for (int rt = 0; rt < 2; rt++)
            #pragma unroll
            for (int nt = 0; nt < 4; nt++)
                #pragma unroll
                for (int q = 0; q < 4; q++) acc[rt][nt][q] = 0.f;

        #pragma unroll
        for (int kk = 0; kk < 16; kk++){
            uint32_t kb = (uint32_t)(kk*16*2);    // k0 bytes
            uint32_t a[2][4];
            ldsm_x4(a[0][0], a[0][1], a[0][2], a[0][3], aAddr0 + kb);
            ldsm_x4(a[1][0], a[1][1], a[1][2], a[1][3], aAddr0 + kb + 16*ASB);
            uint32_t b00, b01, b10, b11, b20, b21, b30, b31;
            ldsm_x4(b00, b10, b01, b11, bAddr0 + kb);             // nt 0,1
            ldsm_x4(b20, b30, b21, b31, bAddr0 + kb + 16*ASB);    // nt 2,3
            mma16816(acc[0][0], a[0], b00, b01);
            mma16816(acc[1][0], a[1], b00, b01);
            mma16816(acc[0][1], a[0], b10, b11);
            mma16816(acc[1][1], a[1], b10, b11);
            mma16816(acc[0][2], a[0], b20, b21);
            mma16816(acc[1][2], a[1], b20, b21);
            mma16816(acc[0][3], a[0], b30, b31);
            mma16816(acc[1][3], a[1], b30, b31);
        }

        #pragma unroll
        for (int rt = 0; rt < 2; rt++){
            int r = i0 + wr*32 + rt*16 + gid;
            #pragma unroll
            for (int nt = 0; nt < 4; nt++){
                int o = wc*32 + nt*8 + tg*2;
                float2 ad = *(const float2*)&addsh[o];
                size_t base = (((size_t)(b*Nn) + r)*Nn + j)*OUTn + o;
                float2 v0 = make_float2(acc[rt][nt][0] + ad.x, acc[rt][nt][1] + ad.y);
                float2 v1 = make_float2(acc[rt][nt][2] + ad.x, acc[rt][nt][3] + ad.y);
                *(float2*)(out + base) = v0;
                *(float2*)(out + base + (size_t)8*Nn*OUTn) = v1;
            }
        }
    }
}

// ---------------- launch ----------------
extern "C" void kernel_launch(void* const* d_in, const int* in_sizes, int n_in,
                              void* d_out, int out_size) {
    const float* x    = (const float*)d_in[0];
    const float* w1nb = (const float*)d_in[1];
    const float* b1nb = (const float*)d_in[2];
    const float* w0nb = (const float*)d_in[3];
    const float* b0nb = (const float*)d_in[4];
    const float* w2d  = (const float*)d_in[5];
    const float* b2d  = (const float*)d_in[6];
    const float* w1d  = (const float*)d_in[7];
    const float* b1d  = (const float*)d_in[8];
    const float* w0d  = (const float*)d_in[9];
    const float* b0d  = (const float*)d_in[10];
    float* out = (float*)d_out;

    cudaFuncSetAttribute(k_main, cudaFuncAttributeMaxDynamicSharedMemorySize, SMEM_MAIN);
    cudaFuncSetAttribute(k_add, cudaFuncAttributeMaxDynamicSharedMemorySize, ADD_SMEM);

    k_sweep1<<<2*Bn*Nn + 64, 256>>>(x, w2d);
    k_neighb<<<Bn, 1024>>>(w1nb, b1nb, w0nb, b0nb);
    k_sweep2<<<2*Bn*Nn, 256>>>(x);
    k_rcs2p<<<Bn*16, 256>>>();
    k_add<<<Bn*64, 256, ADD_SMEM>>>(w1d, w0d, b0d, b1d, b2d);
    k_main<<<Bn*Nn*2/JPB, 256, SMEM_MAIN>>>(x, out);
}

// round 14
// speedup vs baseline: 1.0195x; 1.0195x over previous
#include <cuda_runtime.h>
#include <cuda_fp16.h>
#include <cstdint>

#define Bn 4
#define Nn 256
#define Cc 32
#define Mm 4
#define OUTn 64

// ---------------- scratch (device globals: no allocation allowed) ----------------
__device__ float g_S1[Bn*Nn*Cc];      // rowsum  (mean over axis1)
__device__ float g_S2[Bn*Nn*Cc];      // colsum  (mean over axis2)
__device__ float g_D [Bn*Nn*Cc];      // diag
__device__ float g_p [Bn*Nn*Mm];      // sigmoid neighborhood
__device__ float g_U [Bn*Nn*Mm*Cc];
__device__ float g_V [Bn*Nn*Mm*Cc];
__device__ float g_part1[Bn*16*128];  // rcs2 partials (atomic accum)
__device__ float g_part2[Bn*16*128];  // ds2  partials (atomic accum)
__device__ float g_add[Bn*Nn*OUTn];
__device__ __half g_Wt[OUTn*2*Mm*Cc]; // w2d transposed: Wt[o][k]

// ---------------- sweep 1: rowpass (S2, D) + colpass (S1) + w2d->half + zero partials ----------------
__global__ void k_sweep1(const float* __restrict__ x, const float* __restrict__ w2d){
    int blk = blockIdx.x;
    int tid = threadIdx.x;
    if (blk >= 2*Bn*Nn + 64){
        // zero g_part1/g_part2: 16384 floats = 4096 float4, 16 blocks
        int idx = (blk - (2*Bn*Nn + 64)) * 256 + tid;   // < 4096
        float4 z = make_float4(0.f, 0.f, 0.f, 0.f);
        if (idx < 2048) ((float4*)g_part1)[idx] = z;
        else            ((float4*)g_part2)[idx - 2048] = z;
        return;
    }
    if (blk >= 2*Bn*Nn){
        int idx = (blk - 2*Bn*Nn) * 256 + tid;   // 16384
        int o = idx >> 8, k = idx & 255;
        g_Wt[idx] = __float2half(w2d[k*OUTn + o]);
        return;
    }
    __shared__ float red[8][32];
    int c = tid & 31, g = tid >> 5;
    if (blk < Bn*Nn){
        int bt = blk;
        int t = bt & (Nn-1);
        const float* xrow = x + (size_t)bt * Nn * Cc;
        float s = 0.f;
        #pragma unroll 8
        for (int j = g; j < Nn; j += 8) s += xrow[j*Cc + c];
        red[g][c] = s;
        __syncthreads();
        if (g == 0){
            float tot = 0.f;
            #pragma unroll
            for (int k = 0; k < 8; k++) tot += red[k][c];
            g_S2[bt*Cc + c] = tot * (1.0f/Nn);
            g_D [bt*Cc + c] = xrow[t*Cc + c];
        }
    } else {
        int bt = blk - Bn*Nn;
        int b = bt >> 8, t = bt & (Nn-1);
        const float* xb = x + (size_t)b*Nn*Nn*Cc + (size_t)t*Cc;
        float s = 0.f;
        #pragma unroll 8
        for (int i = g; i < Nn; i += 8) s += xb[(size_t)i*Nn*Cc + c];
        red[g][c] = s;
        __syncthreads();
        if (g == 0){
            float tot = 0.f;
            #pragma unroll
            for (int k = 0; k < 8; k++) tot += red[k][c];
            g_S1[bt*Cc + c] = tot * (1.0f/Nn);
        }
    }
}

// ---------------- neighborhood sigmoid: p[b,t,m], 1024 threads ----------------
__global__ __launch_bounds__(1024) void k_neighb(const float* __restrict__ w1, const float* __restrict__ b1,
                         const float* __restrict__ w0, const float* __restrict__ b0){
    int b = blockIdx.x;
    __shared__ float w1s[3*Cc*Mm];
    __shared__ float w0s[2*Cc*Mm];
    __shared__ float rcs[Cc], ds[Cc], z0[Mm];
    __shared__ float r1[32][32], r2[32][32];
    int tid = threadIdx.x;
    if (tid < 3*Cc*Mm) w1s[tid] = w1[tid];
    if (tid < 2*Cc*Mm) w0s[tid] = w0[tid];
    int c = tid & 31, g = tid >> 5;
    float s1 = 0.f, s2 = 0.f;
    #pragma unroll
    for (int t = g; t < Nn; t += 32){
        s1 += g_S1[(b*Nn + t)*Cc + c];
        s2 += g_D [(b*Nn + t)*Cc + c];
    }
    r1[g][c] = s1; r2[g][c] = s2;
    __syncthreads();
    if (tid < 32){
        float a = 0.f, d = 0.f;
        #pragma unroll
        for (int k = 0; k < 32; k++){ a += r1[k][c]; d += r2[k][c]; }
        rcs[c] = a * (1.0f/Nn);
        ds[c]  = d * (1.0f/Nn);
    }
    __syncthreads();
    if (tid < Mm){
        int m = tid;
        float z = b0[m];
        #pragma unroll
        for (int cc = 0; cc < Cc; cc++)
            z += rcs[cc]*w0s[cc*Mm + m] + ds[cc]*w0s[(Cc+cc)*Mm + m];
        z0[m] = z;
    }
    __syncthreads();
    int t = tid >> 2, m = tid & 3;
    const float* S1r = &g_S1[(b*Nn + t)*Cc];
    const float* S2r = &g_S2[(b*Nn + t)*Cc];
    const float* Dr  = &g_D [(b*Nn + t)*Cc];
    float node = b1[m] + z0[m];
    #pragma unroll
    for (int cc = 0; cc < Cc; cc++)
        node += S1r[cc]*w1s[cc*Mm+m] + S2r[cc]*w1s[(Cc+cc)*Mm+m] + Dr[cc]*w1s[(2*Cc+cc)*Mm+m];
    g_p[(b*Nn + t)*Mm + m] = 1.0f / (1.0f + expf(-node));
}

// ---------------- sweep 2: V/U + rcs2/ds2 partial accumulation (atomics) ----------------
__global__ void k_sweep2(const float* __restrict__ x){
    int blk = blockIdx.x;
    bool is_v = blk < Bn*Nn;
    int bt = is_v ? blk : blk - Bn*Nn;
    int b = bt >> 8, t = bt & (Nn-1);
    const float* base;
    size_t stride;
    if (is_v){ base = x + (size_t)bt * Nn * Cc;              stride = Cc; }
    else     { base = x + (size_t)b*Nn*Nn*Cc + (size_t)t*Cc; stride = (size_t)Nn*Cc; }
    __shared__ float pv[Nn*Mm];
    __shared__ float red[8*Mm*32];
    int tid = threadIdx.x;
    ((float4*)pv)[tid] = ((const float4*)g_p)[b*Nn + tid];
    __syncthreads();
    int c = tid & 31, g = tid >> 5;
    float acc[Mm] = {0.f,0.f,0.f,0.f};
    #pragma unroll 8
    for (int j = g; j < Nn; j += 8){
        float v = base[(size_t)j*stride + c];
        #pragma unroll
        for (int m = 0; m < Mm; m++) acc[m] += v * pv[j*Mm + m];
    }
    #pragma unroll
    for (int m = 0; m < Mm; m++) red[(g*Mm + m)*32 + c] = acc[m];
    __syncthreads();
    if (g < Mm){
        int m = g;
        float s = 0.f;
        #pragma unroll
        for (int k = 0; k < 8; k++) s += red[(k*Mm + m)*32 + c];
        float val = s * (1.0f/Nn);
        if (is_v){
            g_V[(bt*Mm + m)*Cc + c] = val;
            // rcs2 partial: p[t,m] * V[t,m,c] into slice t>>4
            float pt = pv[t*Mm + m];
            atomicAdd(&g_part1[(b*16 + (t >> 4))*128 + m*32 + c], pt * val);
        } else {
            g_U[(bt*Mm + m)*Cc + c] = val;
        }
    } else if (is_v){
        // ds2 partial: p[t,m]^2 * D[t,c] (warps 4-7, m = g-4)
        int m = g - 4;
        float pt = pv[t*Mm + m];
        float dv = g_D[bt*Cc + c];
        atomicAdd(&g_part2[(b*16 + (t >> 4))*128 + m*32 + c], pt * pt * dv);
    }
}

// ---------------- add[b,t,o]: 256 blocks, 4 t per block ----------------
#define ADD_SMEM (4*384*4 + 96*64*4)
__global__ void k_add(const float* __restrict__ w1d, const float* __restrict__ w0d,
                      const float* __restrict__ b0d, const float* __restrict__ b1d,
                      const float* __restrict__ b2d){
    extern __shared__ float ash[];
    float* o1  = ash;
    float* wsh = ash + 4*384;
    __shared__ float rsh[128], dsh[128], zred[256], z0sh[64];
    int b = blockIdx.x >> 6;
    int t0 = (blockIdx.x & 63) * 4;
    int tid = threadIdx.x;

    #pragma unroll
    for (int it = 0; it < 6; it++){
        int idx = tid + it*256;
        int tl = idx / 384, k = idx - tl*384;
        int t = t0 + tl;
        int seg = k >> 7, mc = k & 127;
        int m = mc >> 5, c = mc & 31;
        float pv = g_p[(b*Nn + t)*Mm + m];
        float val;
        if (seg == 0)      val = pv * g_U[((b*Nn + t)*Mm + m)*Cc + c];
        else if (seg == 1) val = pv * g_V[((b*Nn + t)*Mm + m)*Cc + c];
        else               val = pv * pv * g_D[(b*Nn + t)*Cc + c];
        o1[idx] = val;
    }
    if (tid < 128){
        float a = 0.f, d = 0.f;
        #pragma unroll
        for (int s = 0; s < 16; s++){
            a += g_part1[(b*16 + s)*128 + tid];
            d += g_part2[(b*16 + s)*128 + tid];
        }
        rsh[tid] = a * (1.0f/Nn);
        dsh[tid] = d * (1.0f/Nn);
    }
    __syncthreads();
    {
        int o = tid & 63, q = tid >> 6;
        float s = 0.f;
        int k0 = q*32;
        #pragma unroll
        for (int k = k0; k < k0+32; k++)
            s += rsh[k]*w0d[k*OUTn + o] + dsh[k]*w0d[(128+k)*OUTn + o];
        zred[tid] = s;
    }
    __syncthreads();
    if (tid < 64)
        z0sh[tid] = zred[tid] + zred[tid+64] + zred[tid+128] + zred[tid+192]
                  + b0d[tid] + b1d[tid] + b2d[tid];

    int tq = tid >> 6, o = tid & 63;
    float acc = 0.f;
    #pragma unroll
    for (int chunk = 0; chunk < 4; chunk++){
        __syncthreads();
        {
            const float4* w4 = (const float4*)(w1d + chunk*96*64);
            #pragma unroll
            for (int it = 0; it < 6; it++)
                ((float4*)wsh)[tid + it*256] = w4[tid + it*256];
        }
        __syncthreads();
        #pragma unroll 8
        for (int k = 0; k < 96; k++)
            acc += o1[tq*384 + chunk*96 + k] * wsh[k*64 + o];
    }
    g_add[(b*Nn + t0 + tq)*OUTn + o] = acc + z0sh[o];
}

// ---------------- main fused GEMM: JPB 4, ldmatrix fragment loads ----------------
__device__ __forceinline__ void mma16816(float* c, const uint32_t* a, uint32_t b0, uint32_t b1){
    asm volatile("mma.sync.aligned.m16n8k16.row.col.f32.f16.f16.f32 "
        "{%0,%1,%2,%3}, {%4,%5,%6,%7}, {%8,%9}, {%0,%1,%2,%3};\n"
        : "+f"(c[0]), "+f"(c[1]), "+f"(c[2]), "+f"(c[3])
        : "r"(a[0]), "r"(a[1]), "r"(a[2]), "r"(a[3]), "r"(b0), "r"(b1));
}
__device__ __forceinline__ void ldsm_x4(uint32_t& r0, uint32_t& r1, uint32_t& r2, uint32_t& r3, uint32_t addr){
    asm volatile("ldmatrix.sync.aligned.m8n8.x4.shared.b16 {%0,%1,%2,%3}, [%4];"
        : "=r"(r0), "=r"(r1), "=r"(r2), "=r"(r3) : "r"(addr));
}
__device__ __forceinline__ uint32_t smem_u32(const void* p){
    uint32_t a;
    asm("{ .reg .u64 t; cvta.to.shared.u64 t, %1; cvt.u32.u64 %0, t; }" : "=r"(a) : "l"(p));
    return a;
}

#define AS 264
#define ASB (AS*2)
#define SMEM_MAIN (128*AS*2 + 64*AS*2 + 512*4 + 64*4)
#define JPB 4

__global__ __launch_bounds__(256, 2) void k_main(const float* __restrict__ x, float* __restrict__ out){
    extern __shared__ __align__(16) char smem[];
    __half* Ash  = (__half*)smem;
    __half* Wsh  = Ash + 128*AS;
    float*  sshf = (float*)(Wsh + 64*AS);
    float*  addsh = sshf + 512;

    int blk = blockIdx.x;
    int ib = blk & 1, jp = (blk >> 1) & 63, b = blk >> 7;
    int i0 = ib * 128;
    int tid = threadIdx.x;

    {
        const uint4* Wt4 = (const uint4*)g_Wt;
        #pragma unroll
        for (int it = 0; it < 8; it++){
            int idx = tid + it*256;
            int o = idx >> 5, kq = idx & 31;
            *(uint4*)&Wsh[o*AS + kq*8] = Wt4[idx];
        }
    }
    if (tid < 128)
        ((float4*)sshf)[tid] = ((const float4*)g_p)[b*Nn + i0 + tid];
    __syncthreads();

    int lane = tid & 31, wid = tid >> 5;
    int wr = wid >> 1, wc = wid & 1;
    int gid = lane >> 2, tg = lane & 3;

    uint32_t ash_u = smem_u32(Ash);
    uint32_t wsh_u = smem_u32(Wsh);
    int lrow = lane & 15, lsel = lane >> 4;
    uint32_t aAddr0 = ash_u + (uint32_t)(wr*32 + lrow)*ASB + (uint32_t)lsel*16;
    uint32_t bAddr0 = wsh_u + (uint32_t)(wc*32 + lrow)*ASB + (uint32_t)lsel*16;

    float2 vc[8];
    float4 pjv;
    float  addv;
    {
        int j = jp*JPB;
        size_t base_c = (((size_t)(b*Nn) + i0)*Nn + j)*Cc;
        #pragma unroll
        for (int it = 0; it < 8; it++){
            int idx = tid + it*256;
            int i = idx >> 4, cp = idx & 15;
            vc[it] = *(const float2*)(x + base_c + (size_t)i*(Nn*Cc) + cp*2);
        }
        pjv  = ((const float4*)g_p)[b*Nn + j];
        addv = g_add[(b*Nn + j)*OUTn + (tid & 63)];
    }

    for (int jj = 0; jj < JPB; jj++){
        int j = jp*JPB + jj;
        if (jj > 0) __syncthreads();

        {
            size_t base_r = (((size_t)(b*Nn) + j)*Nn + i0)*Cc;
            #pragma unroll
            for (int it = 0; it < 8; it++){
                int idx = tid + it*256;
                int i = idx >> 4, cp = idx & 15;
                float4 pi = ((const float4*)sshf)[i];
                float4 s = make_float4(pi.x*pjv.x, pi.y*pjv.y, pi.z*pjv.z, pi.w*pjv.w);
                float2 v = vc[it];
                __half* arow = Ash + i*AS + cp*2;
                *(half2*)(arow     ) = __floats2half2_rn(s.x*v.x, s.x*v.y);
                *(half2*)(arow + 32) = __floats2half2_rn(s.y*v.x, s.y*v.y);
                *(half2*)(arow + 64) = __floats2half2_rn(s.z*v.x, s.z*v.y);
                *(half2*)(arow + 96) = __floats2half2_rn(s.w*v.x, s.w*v.y);
                float2 w = *(const float2*)(x + base_r + (size_t)i*Cc + cp*2);
                __half* brow = arow + 128;
                *(half2*)(brow     ) = __floats2half2_rn(s.x*w.x, s.x*w.y);
                *(half2*)(brow + 32) = __floats2half2_rn(s.y*w.x, s.y*w.y);
                *(half2*)(brow + 64) = __floats2half2_rn(s.z*w.x, s.z*w.y);
                *(half2*)(brow + 96) = __floats2half2_rn(s.w*w.x, s.w*w.y);
            }
            if (tid < 64) addsh[tid] = addv;
        }
        __syncthreads();

        if (jj + 1 < JPB){
            int j2 = j + 1;
            size_t base_c = (((size_t)(b*Nn) + i0)*Nn + j2)*Cc;
            #pragma unroll
            for (int it = 0; it < 8; it++){
                int idx = tid + it*256;
                int i = idx >> 4, cp = idx & 15;
                vc[it] = *(const float2*)(x + base_c + (size_t)i*(Nn*Cc) + cp*2);
            }
            pjv  = ((const float4*)g_p)[b*Nn + j2];
            addv = g_add[(b*Nn + j2)*OUTn + (tid & 63)];
        }

        float acc[2][4][4];
        #pragma unroll
        for (int rt = 0; rt < 2; rt++)
            #pragma unroll
            for (int nt = 0; nt < 4; nt++)
                #pragma unroll
                for (int q = 0; q < 4; q++) acc[rt][nt][q] = 0.f;

        #pragma unroll
        for (int kk = 0; kk < 16; kk++){
            uint32_t kb = (uint32_t)(kk*16*2);
            uint32_t a[2][4];
            ldsm_x4(a[0][0], a[0][1], a[0][2], a[0][3], aAddr0 + kb);
            ldsm_x4(a[1][0], a[1][1], a[1][2], a[1][3], aAddr0 + kb + 16*ASB);
            uint32_t b00, b01, b10, b11, b20, b21, b30, b31;
            ldsm_x4(b00, b10, b01, b11, bAddr0 + kb);
            ldsm_x4(b20, b30, b21, b31, bAddr0 + kb + 16*ASB);
            mma16816(acc[0][0], a[0], b00, b01);
            mma16816(acc[1][0], a[1], b00, b01);
            mma16816(acc[0][1], a[0], b10, b11);
            mma16816(acc[1][1], a[1], b10, b11);
            mma16816(acc[0][2], a[0], b20, b21);
            mma16816(acc[1][2], a[1], b20, b21);
            mma16816(acc[0][3], a[0], b30, b31);
            mma16816(acc[1][3], a[1], b30, b31);
        }

        #pragma unroll
        for (int rt = 0; rt < 2; rt++){
            int r = i0 + wr*32 + rt*16 + gid;
            #pragma unroll
            for (int nt = 0; nt < 4; nt++){
                int o = wc*32 + nt*8 + tg*2;
                float2 ad = *(const float2*)&addsh[o];
                size_t base = (((size_t)(b*Nn) + r)*Nn + j)*OUTn + o;
                float2 v0 = make_float2(acc[rt][nt][0] + ad.x, acc[rt][nt][1] + ad.y);
                float2 v1 = make_float2(acc[rt][nt][2] + ad.x, acc[rt][nt][3] + ad.y);
                *(float2*)(out + base) = v0;
                *(float2*)(out + base + (size_t)8*Nn*OUTn) = v1;
            }
        }
    }
}

// ---------------- launch ----------------
extern "C" void kernel_launch(void* const* d_in, const int* in_sizes, int n_in,
                              void* d_out, int out_size) {
    const float* x    = (const float*)d_in[0];
    const float* w1nb = (const float*)d_in[1];
    const float* b1nb = (const float*)d_in[2];
    const float* w0nb = (const float*)d_in[3];
    const float* b0nb = (const float*)d_in[4];
    const float* w2d  = (const float*)d_in[5];
    const float* b2d  = (const float*)d_in[6];
    const float* w1d  = (const float*)d_in[7];
    const float* b1d  = (const float*)d_in[8];
    const float* w0d  = (const float*)d_in[9];
    const float* b0d  = (const float*)d_in[10];
    float* out = (float*)d_out;

    cudaFuncSetAttribute(k_main, cudaFuncAttributeMaxDynamicSharedMemorySize, SMEM_MAIN);
    cudaFuncSetAttribute(k_add, cudaFuncAttributeMaxDynamicSharedMemorySize, ADD_SMEM);

    k_sweep1<<<2*Bn*Nn + 64 + 16, 256>>>(x, w2d);   // +16 blocks zero the partials
    k_neighb<<<Bn, 1024>>>(w1nb, b1nb, w0nb, b0nb);
    k_sweep2<<<2*Bn*Nn, 256>>>(x);
    k_add<<<Bn*64, 256, ADD_SMEM>>>(w1d, w0d, b0d, b1d, b2d);
    k_main<<<Bn*Nn*2/JPB, 256, SMEM_MAIN>>>(x, out);
}

// round 15
// speedup vs baseline: 1.0223x; 1.0027x over previous
#include <cuda_runtime.h>
#include <cuda_fp16.h>
#include <cstdint>

#define Bn 4
#define Nn 256
#define Cc 32
#define Mm 4
#define OUTn 64

// ---------------- scratch (device globals: no allocation allowed) ----------------
__device__ float g_S1[Bn*Nn*Cc];      // rowsum  (mean over axis1)
__device__ float g_S2[Bn*Nn*Cc];      // colsum  (mean over axis2)
__device__ float g_D [Bn*Nn*Cc];      // diag
__device__ float g_p [Bn*Nn*Mm];      // sigmoid neighborhood
__device__ float g_U [Bn*Nn*Mm*Cc];
__device__ float g_V [Bn*Nn*Mm*Cc];
__device__ float g_part1[Bn*16*128];  // rcs2 partials (atomic accum)
__device__ float g_part2[Bn*16*128];  // ds2  partials (atomic accum)
__device__ float g_add[Bn*Nn*OUTn];
__device__ __half g_Wt[OUTn*2*Mm*Cc]; // w2d transposed: Wt[o][k]

// ---------------- sweep 1: rowpass (S2, D) + colpass (S1) + w2d->half + zero partials ----------------
__global__ void k_sweep1(const float* __restrict__ x, const float* __restrict__ w2d){
    int blk = blockIdx.x;
    int tid = threadIdx.x;
    if (blk >= 2*Bn*Nn + 64){
        // zero g_part1/g_part2: 16384 floats = 4096 float4, 16 blocks
        int idx = (blk - (2*Bn*Nn + 64)) * 256 + tid;   // < 4096
        float4 z = make_float4(0.f, 0.f, 0.f, 0.f);
        if (idx < 2048) ((float4*)g_part1)[idx] = z;
        else            ((float4*)g_part2)[idx - 2048] = z;
        return;
    }
    if (blk >= 2*Bn*Nn){
        int idx = (blk - 2*Bn*Nn) * 256 + tid;   // 16384
        int o = idx >> 8, k = idx & 255;
        g_Wt[idx] = __float2half(w2d[k*OUTn + o]);
        return;
    }
    __shared__ float red[8][32];
    int c = tid & 31, g = tid >> 5;
    if (blk < Bn*Nn){
        int bt = blk;
        int t = bt & (Nn-1);
        const float* xrow = x + (size_t)bt * Nn * Cc;
        float s = 0.f;
        #pragma unroll 8
        for (int j = g; j < Nn; j += 8) s += xrow[j*Cc + c];
        red[g][c] = s;
        __syncthreads();
        if (g == 0){
            float tot = 0.f;
            #pragma unroll
            for (int k = 0; k < 8; k++) tot += red[k][c];
            g_S2[bt*Cc + c] = tot * (1.0f/Nn);
            g_D [bt*Cc + c] = xrow[t*Cc + c];
        }
    } else {
        int bt = blk - Bn*Nn;
        int b = bt >> 8, t = bt & (Nn-1);
        const float* xb = x + (size_t)b*Nn*Nn*Cc + (size_t)t*Cc;
        float s = 0.f;
        #pragma unroll 8
        for (int i = g; i < Nn; i += 8) s += xb[(size_t)i*Nn*Cc + c];
        red[g][c] = s;
        __syncthreads();
        if (g == 0){
            float tot = 0.f;
            #pragma unroll
            for (int k = 0; k < 8; k++) tot += red[k][c];
            g_S1[bt*Cc + c] = tot * (1.0f/Nn);
        }
    }
}

// ---------------- neighborhood sigmoid: p[b,t,m], 1024 threads ----------------
__global__ __launch_bounds__(1024) void k_neighb(const float* __restrict__ w1, const float* __restrict__ b1,
                         const float* __restrict__ w0, const float* __restrict__ b0){
    int b = blockIdx.x;
    __shared__ float w1s[3*Cc*Mm];
    __shared__ float w0s[2*Cc*Mm];
    __shared__ float rcs[Cc], ds[Cc], z0[Mm];
    __shared__ float r1[32][32], r2[32][32];
    int tid = threadIdx.x;
    if (tid < 3*Cc*Mm) w1s[tid] = w1[tid];
    if (tid < 2*Cc*Mm) w0s[tid] = w0[tid];
    int c = tid & 31, g = tid >> 5;
    float s1 = 0.f, s2 = 0.f;
    #pragma unroll
    for (int t = g; t < Nn; t += 32){
        s1 += g_S1[(b*Nn + t)*Cc + c];
        s2 += g_D [(b*Nn + t)*Cc + c];
    }
    r1[g][c] = s1; r2[g][c] = s2;
    __syncthreads();
    if (tid < 32){
        float a = 0.f, d = 0.f;
        #pragma unroll
        for (int k = 0; k < 32; k++){ a += r1[k][c]; d += r2[k][c]; }
        rcs[c] = a * (1.0f/Nn);
        ds[c]  = d * (1.0f/Nn);
    }
    __syncthreads();
    if (tid < Mm){
        int m = tid;
        float z = b0[m];
        #pragma unroll
        for (int cc = 0; cc < Cc; cc++)
            z += rcs[cc]*w0s[cc*Mm + m] + ds[cc]*w0s[(Cc+cc)*Mm + m];
        z0[m] = z;
    }
    __syncthreads();
    int t = tid >> 2, m = tid & 3;
    const float* S1r = &g_S1[(b*Nn + t)*Cc];
    const float* S2r = &g_S2[(b*Nn + t)*Cc];
    const float* Dr  = &g_D [(b*Nn + t)*Cc];
    float node = b1[m] + z0[m];
    #pragma unroll
    for (int cc = 0; cc < Cc; cc++)
        node += S1r[cc]*w1s[cc*Mm+m] + S2r[cc]*w1s[(Cc+cc)*Mm+m] + Dr[cc]*w1s[(2*Cc+cc)*Mm+m];
    g_p[(b*Nn + t)*Mm + m] = 1.0f / (1.0f + expf(-node));
}

// ---------------- sweep 2: V/U + rcs2/ds2 partial accumulation (atomics) ----------------
__global__ void k_sweep2(const float* __restrict__ x){
    int blk = blockIdx.x;
    bool is_v = blk < Bn*Nn;
    int bt = is_v ? blk : blk - Bn*Nn;
    int b = bt >> 8, t = bt & (Nn-1);
    const float* base;
    size_t stride;
    if (is_v){ base = x + (size_t)bt * Nn * Cc;              stride = Cc; }
    else     { base = x + (size_t)b*Nn*Nn*Cc + (size_t)t*Cc; stride = (size_t)Nn*Cc; }
    __shared__ float pv[Nn*Mm];
    __shared__ float red[8*Mm*32];
    int tid = threadIdx.x;
    ((float4*)pv)[tid] = ((const float4*)g_p)[b*Nn + tid];
    __syncthreads();
    int c = tid & 31, g = tid >> 5;
    float acc[Mm] = {0.f,0.f,0.f,0.f};
    #pragma unroll 8
    for (int j = g; j < Nn; j += 8){
        float v = base[(size_t)j*stride + c];
        #pragma unroll
        for (int m = 0; m < Mm; m++) acc[m] += v * pv[j*Mm + m];
    }
    #pragma unroll
    for (int m = 0; m < Mm; m++) red[(g*Mm + m)*32 + c] = acc[m];
    __syncthreads();
    if (g < Mm){
        int m = g;
        float s = 0.f;
        #pragma unroll
        for (int k = 0; k < 8; k++) s += red[(k*Mm + m)*32 + c];
        float val = s * (1.0f/Nn);
        if (is_v){
            g_V[(bt*Mm + m)*Cc + c] = val;
            float pt = pv[t*Mm + m];
            atomicAdd(&g_part1[(b*16 + (t >> 4))*128 + m*32 + c], pt * val);
        } else {
            g_U[(bt*Mm + m)*Cc + c] = val;
        }
    } else if (is_v){
        int m = g - 4;
        float pt = pv[t*Mm + m];
        float dv = g_D[bt*Cc + c];
        atomicAdd(&g_part2[(b*16 + (t >> 4))*128 + m*32 + c], pt * pt * dv);
    }
}

// ---------------- add[b,t,o]: 256 blocks, 4 t per block, 4-way accumulator split ----------------
#define ADD_SMEM (4*384*4 + 96*64*4)
__global__ void k_add(const float* __restrict__ w1d, const float* __restrict__ w0d,
                      const float* __restrict__ b0d, const float* __restrict__ b1d,
                      const float* __restrict__ b2d){
    extern __shared__ float ash[];
    float* o1  = ash;
    float* wsh = ash + 4*384;
    __shared__ float rsh[128], dsh[128], zred[256], z0sh[64];
    int b = blockIdx.x >> 6;
    int t0 = (blockIdx.x & 63) * 4;
    int tid = threadIdx.x;

    #pragma unroll
    for (int it = 0; it < 6; it++){
        int idx = tid + it*256;
        int tl = idx / 384, k = idx - tl*384;
        int t = t0 + tl;
        int seg = k >> 7, mc = k & 127;
        int m = mc >> 5, c = mc & 31;
        float pv = g_p[(b*Nn + t)*Mm + m];
        float val;
        if (seg == 0)      val = pv * g_U[((b*Nn + t)*Mm + m)*Cc + c];
        else if (seg == 1) val = pv * g_V[((b*Nn + t)*Mm + m)*Cc + c];
        else               val = pv * pv * g_D[(b*Nn + t)*Cc + c];
        o1[idx] = val;
    }
    if (tid < 128){
        float a = 0.f, d = 0.f;
        #pragma unroll
        for (int s = 0; s < 16; s++){
            a += g_part1[(b*16 + s)*128 + tid];
            d += g_part2[(b*16 + s)*128 + tid];
        }
        rsh[tid] = a * (1.0f/Nn);
        dsh[tid] = d * (1.0f/Nn);
    }
    __syncthreads();
    {
        int o = tid & 63, q = tid >> 6;
        float s = 0.f;
        int k0 = q*32;
        #pragma unroll
        for (int k = k0; k < k0+32; k++)
            s += rsh[k]*w0d[k*OUTn + o] + dsh[k]*w0d[(128+k)*OUTn + o];
        zred[tid] = s;
    }
    __syncthreads();
    if (tid < 64)
        z0sh[tid] = zred[tid] + zred[tid+64] + zred[tid+128] + zred[tid+192]
                  + b0d[tid] + b1d[tid] + b2d[tid];

    int tq = tid >> 6, o = tid & 63;
    float ac0 = 0.f, ac1 = 0.f, ac2 = 0.f, ac3 = 0.f;   // 4 independent chains
    #pragma unroll
    for (int chunk = 0; chunk < 4; chunk++){
        __syncthreads();
        {
            const float4* w4 = (const float4*)(w1d + chunk*96*64);
            #pragma unroll
            for (int it = 0; it < 6; it++)
                ((float4*)wsh)[tid + it*256] = w4[tid + it*256];
        }
        __syncthreads();
        const float* ob = o1 + tq*384 + chunk*96;
        #pragma unroll 6
        for (int k = 0; k < 96; k += 4){
            ac0 += ob[k    ] * wsh[(k    )*64 + o];
            ac1 += ob[k + 1] * wsh[(k + 1)*64 + o];
            ac2 += ob[k + 2] * wsh[(k + 2)*64 + o];
            ac3 += ob[k + 3] * wsh[(k + 3)*64 + o];
        }
    }
    float acc = (ac0 + ac1) + (ac2 + ac3);
    g_add[(b*Nn + t0 + tq)*OUTn + o] = acc + z0sh[o];
}

// ---------------- main fused GEMM: JPB 4, ldmatrix fragment loads ----------------
__device__ __forceinline__ void mma16816(float* c, const uint32_t* a, uint32_t b0, uint32_t b1){
    asm volatile("mma.sync.aligned.m16n8k16.row.col.f32.f16.f16.f32 "
        "{%0,%1,%2,%3}, {%4,%5,%6,%7}, {%8,%9}, {%0,%1,%2,%3};\n"
        : "+f"(c[0]), "+f"(c[1]), "+f"(c[2]), "+f"(c[3])
        : "r"(a[0]), "r"(a[1]), "r"(a[2]), "r"(a[3]), "r"(b0), "r"(b1));
}
__device__ __forceinline__ void ldsm_x4(uint32_t& r0, uint32_t& r1, uint32_t& r2, uint32_t& r3, uint32_t addr){
    asm volatile("ldmatrix.sync.aligned.m8n8.x4.shared.b16 {%0,%1,%2,%3}, [%4];"
        : "=r"(r0), "=r"(r1), "=r"(r2), "=r"(r3) : "r"(addr));
}
__device__ __forceinline__ uint32_t smem_u32(const void* p){
    uint32_t a;
    asm("{ .reg .u64 t; cvta.to.shared.u64 t, %1; cvt.u32.u64 %0, t; }" : "=r"(a) : "l"(p));
    return a;
}

#define AS 264
#define ASB (AS*2)
#define SMEM_MAIN (128*AS*2 + 64*AS*2 + 512*4 + 64*4)
#define JPB 4

__global__ __launch_bounds__(256, 2) void k_main(const float* __restrict__ x, float* __restrict__ out){
    extern __shared__ __align__(16) char smem[];
    __half* Ash  = (__half*)smem;
    __half* Wsh  = Ash + 128*AS;
    float*  sshf = (float*)(Wsh + 64*AS);
    float*  addsh = sshf + 512;

    int blk = blockIdx.x;
    int ib = blk & 1, jp = (blk >> 1) & 63, b = blk >> 7;
    int i0 = ib * 128;
    int tid = threadIdx.x;

    {
        const uint4* Wt4 = (const uint4*)g_Wt;
        #pragma unroll
        for (int it = 0; it < 8; it++){
            int idx = tid + it*256;
            int o = idx >> 5, kq = idx & 31;
            *(uint4*)&Wsh[o*AS + kq*8] = Wt4[idx];
        }
    }
    if (tid < 128)
        ((float4*)sshf)[tid] = ((const float4*)g_p)[b*Nn + i0 + tid];
    __syncthreads();

    int lane = tid & 31, wid = tid >> 5;
    int wr = wid >> 1, wc = wid & 1;
    int gid = lane >> 2, tg = lane & 3;

    uint32_t ash_u = smem_u32(Ash);
    uint32_t wsh_u = smem_u32(Wsh);
    int lrow = lane & 15, lsel = lane >> 4;
    uint32_t aAddr0 = ash_u + (uint32_t)(wr*32 + lrow)*ASB + (uint32_t)lsel*16;
    uint32_t bAddr0 = wsh_u + (uint32_t)(wc*32 + lrow)*ASB + (uint32_t)lsel*16;

    float2 vc[8];
    float4 pjv;
    float  addv;
    {
        int j = jp*JPB;
        size_t base_c = (((size_t)(b*Nn) + i0)*Nn + j)*Cc;
        #pragma unroll
        for (int it = 0; it < 8; it++){
            int idx = tid + it*256;
            int i = idx >> 4, cp = idx & 15;
            vc[it] = *(const float2*)(x + base_c + (size_t)i*(Nn*Cc) + cp*2);
        }
        pjv  = ((const float4*)g_p)[b*Nn + j];
        addv = g_add[(b*Nn + j)*OUTn + (tid & 63)];
    }

    for (int jj = 0; jj < JPB; jj++){
        int j = jp*JPB + jj;
        if (jj > 0) __syncthreads();

        {
            size_t base_r = (((size_t)(b*Nn) + j)*Nn + i0)*Cc;
            #pragma unroll
            for (int it = 0; it < 8; it++){
                int idx = tid + it*256;
                int i = idx >> 4, cp = idx & 15;
                float4 pi = ((const float4*)sshf)[i];
                float4 s = make_float4(pi.x*pjv.x, pi.y*pjv.y, pi.z*pjv.z, pi.w*pjv.w);
                float2 v = vc[it];
                __half* arow = Ash + i*AS + cp*2;
                *(half2*)(arow     ) = __floats2half2_rn(s.x*v.x, s.x*v.y);
                *(half2*)(arow + 32) = __floats2half2_rn(s.y*v.x, s.y*v.y);
                *(half2*)(arow + 64) = __floats2half2_rn(s.z*v.x, s.z*v.y);
                *(half2*)(arow + 96) = __floats2half2_rn(s.w*v.x, s.w*v.y);
                float2 w = *(const float2*)(x + base_r + (size_t)i*Cc + cp*2);
                __half* brow = arow + 128;
                *(half2*)(brow     ) = __floats2half2_rn(s.x*w.x, s.x*w.y);
                *(half2*)(brow + 32) = __floats2half2_rn(s.y*w.x, s.y*w.y);
                *(half2*)(brow + 64) = __floats2half2_rn(s.z*w.x, s.z*w.y);
                *(half2*)(brow + 96) = __floats2half2_rn(s.w*w.x, s.w*w.y);
            }
            if (tid < 64) addsh[tid] = addv;
        }
        __syncthreads();

        if (jj + 1 < JPB){
            int j2 = j + 1;
            size_t base_c = (((size_t)(b*Nn) + i0)*Nn + j2)*Cc;
            #pragma unroll
            for (int it = 0; it < 8; it++){
                int idx = tid + it*256;
                int i = idx >> 4, cp = idx & 15;
                vc[it] = *(const float2*)(x + base_c + (size_t)i*(Nn*Cc) + cp*2);
            }
            pjv  = ((const float4*)g_p)[b*Nn + j2];
            addv = g_add[(b*Nn + j2)*OUTn + (tid & 63)];
        }

        float acc[2][4][4];
        #pragma unroll
        for (int rt = 0; rt < 2; rt++)
            #pragma unroll
            for (int nt = 0; nt < 4; nt++)
                #pragma unroll
                for (int q = 0; q < 4; q++) acc[rt][nt][q] = 0.f;

        #pragma unroll
        for (int kk = 0; kk < 16; kk++){
            uint32_t kb = (uint32_t)(kk*16*2);
            uint32_t a[2][4];
            ldsm_x4(a[0][0], a[0][1], a[0][2], a[0][3], aAddr0 + kb);
            ldsm_x4(a[1][0], a[1][1], a[1][2], a[1][3], aAddr0 + kb + 16*ASB);
            uint32_t b00, b01, b10, b11, b20, b21, b30, b31;
            ldsm_x4(b00, b10, b01, b11, bAddr0 + kb);
            ldsm_x4(b20, b30, b21, b31, bAddr0 + kb + 16*ASB);
            mma16816(acc[0][0], a[0], b00, b01);
            mma16816(acc[1][0], a[1], b00, b01);
            mma16816(acc[0][1], a[0], b10, b11);
            mma16816(acc[1][1], a[1], b10, b11);
            mma16816(acc[0][2], a[0], b20, b21);
            mma16816(acc[1][2], a[1], b20, b21);
            mma16816(acc[0][3], a[0], b30, b31);
            mma16816(acc[1][3], a[1], b30, b31);
        }

        #pragma unroll
        for (int rt = 0; rt < 2; rt++){
            int r = i0 + wr*32 + rt*16 + gid;
            #pragma unroll
            for (int nt = 0; nt < 4; nt++){
                int o = wc*32 + nt*8 + tg*2;
                float2 ad = *(const float2*)&addsh[o];
                size_t base = (((size_t)(b*Nn) + r)*Nn + j)*OUTn + o;
                float2 v0 = make_float2(acc[rt][nt][0] + ad.x, acc[rt][nt][1] + ad.y);
                float2 v1 = make_float2(acc[rt][nt][2] + ad.x, acc[rt][nt][3] + ad.y);
                *(float2*)(out + base) = v0;
                *(float2*)(out + base + (size_t)8*Nn*OUTn) = v1;
            }
        }
    }
}

// ---------------- launch ----------------
extern "C" void kernel_launch(void* const* d_in, const int* in_sizes, int n_in,
                              void* d_out, int out_size) {
    const float* x    = (const float*)d_in[0];
    const float* w1nb = (const float*)d_in[1];
    const float* b1nb = (const float*)d_in[2];
    const float* w0nb = (const float*)d_in[3];
    const float* b0nb = (const float*)d_in[4];
    const float* w2d  = (const float*)d_in[5];
    const float* b2d  = (const float*)d_in[6];
    const float* w1d  = (const float*)d_in[7];
    const float* b1d  = (const float*)d_in[8];
    const float* w0d  = (const float*)d_in[9];
    const float* b0d  = (const float*)d_in[10];
    float* out = (float*)d_out;

    cudaFuncSetAttribute(k_main, cudaFuncAttributeMaxDynamicSharedMemorySize, SMEM_MAIN);
    cudaFuncSetAttribute(k_add, cudaFuncAttributeMaxDynamicSharedMemorySize, ADD_SMEM);

    k_sweep1<<<2*Bn*Nn + 64 + 16, 256>>>(x, w2d);   // +16 blocks zero the partials
    k_neighb<<<Bn, 1024>>>(w1nb, b1nb, w0nb, b0nb);
    k_sweep2<<<2*Bn*Nn, 256>>>(x);
    k_add<<<Bn*64, 256, ADD_SMEM>>>(w1d, w0d, b0d, b1d, b2d);
    k_main<<<Bn*Nn*2/JPB, 256, SMEM_MAIN>>>(x, out);
}

// round 16
// speedup vs baseline: 1.0267x; 1.0043x over previous
#include <cuda_runtime.h>
#include <cuda_fp16.h>
#include <cstdint>

#define Bn 4
#define Nn 256
#define Cc 32
#define Mm 4
#define OUTn 64

// ---------------- scratch (device globals: no allocation allowed) ----------------
__device__ float g_S1[Bn*Nn*Cc];      // rowsum  (mean over axis1)
__device__ float g_S2[Bn*Nn*Cc];      // colsum  (mean over axis2)
__device__ float g_D [Bn*Nn*Cc];      // diag
__device__ float g_p [Bn*Nn*Mm];      // sigmoid neighborhood
__device__ float g_U [Bn*Nn*Mm*Cc];
__device__ float g_V [Bn*Nn*Mm*Cc];
__device__ float g_part1[Bn*16*128];  // rcs2 partials (atomic accum)
__device__ float g_part2[Bn*16*128];  // ds2  partials (atomic accum)
__device__ float g_add[Bn*Nn*OUTn];
__device__ __half g_Wt[OUTn*2*Mm*Cc]; // w2d transposed: Wt[o][k]

// ---------------- sweep 1: rowpass (S2, D) + colpass (S1) + w2d->half + zero partials ----------------
__global__ void k_sweep1(const float* __restrict__ x, const float* __restrict__ w2d){
    int blk = blockIdx.x;
    int tid = threadIdx.x;
    if (blk >= 2*Bn*Nn + 64){
        int idx = (blk - (2*Bn*Nn + 64)) * 256 + tid;   // < 4096
        float4 z = make_float4(0.f, 0.f, 0.f, 0.f);
        if (idx < 2048) ((float4*)g_part1)[idx] = z;
        else            ((float4*)g_part2)[idx - 2048] = z;
        return;
    }
    if (blk >= 2*Bn*Nn){
        int idx = (blk - 2*Bn*Nn) * 256 + tid;   // 16384
        int o = idx >> 8, k = idx & 255;
        g_Wt[idx] = __float2half(w2d[k*OUTn + o]);
        return;
    }
    __shared__ float red[8][32];
    int c = tid & 31, g = tid >> 5;
    if (blk < Bn*Nn){
        int bt = blk;
        int t = bt & (Nn-1);
        const float* xrow = x + (size_t)bt * Nn * Cc;
        float s = 0.f;
        #pragma unroll 8
        for (int j = g; j < Nn; j += 8) s += xrow[j*Cc + c];
        red[g][c] = s;
        __syncthreads();
        if (g == 0){
            float tot = 0.f;
            #pragma unroll
            for (int k = 0; k < 8; k++) tot += red[k][c];
            g_S2[bt*Cc + c] = tot * (1.0f/Nn);
            g_D [bt*Cc + c] = xrow[t*Cc + c];
        }
    } else {
        int bt = blk - Bn*Nn;
        int b = bt >> 8, t = bt & (Nn-1);
        const float* xb = x + (size_t)b*Nn*Nn*Cc + (size_t)t*Cc;
        float s = 0.f;
        #pragma unroll 8
        for (int i = g; i < Nn; i += 8) s += xb[(size_t)i*Nn*Cc + c];
        red[g][c] = s;
        __syncthreads();
        if (g == 0){
            float tot = 0.f;
            #pragma unroll
            for (int k = 0; k < 8; k++) tot += red[k][c];
            g_S1[bt*Cc + c] = tot * (1.0f/Nn);
        }
    }
}

// ---------------- neighborhood sigmoid: p[b,t,m], 1024 threads ----------------
__global__ __launch_bounds__(1024) void k_neighb(const float* __restrict__ w1, const float* __restrict__ b1,
                         const float* __restrict__ w0, const float* __restrict__ b0){
    int b = blockIdx.x;
    __shared__ float w1s[3*Cc*Mm];
    __shared__ float w0s[2*Cc*Mm];
    __shared__ float rcs[Cc], ds[Cc], z0[Mm];
    __shared__ float r1[32][32], r2[32][32];
    int tid = threadIdx.x;
    if (tid < 3*Cc*Mm) w1s[tid] = w1[tid];
    if (tid < 2*Cc*Mm) w0s[tid] = w0[tid];
    int c = tid & 31, g = tid >> 5;
    float s1 = 0.f, s2 = 0.f;
    #pragma unroll
    for (int t = g; t < Nn; t += 32){
        s1 += g_S1[(b*Nn + t)*Cc + c];
        s2 += g_D [(b*Nn + t)*Cc + c];
    }
    r1[g][c] = s1; r2[g][c] = s2;
    __syncthreads();
    if (tid < 32){
        float a = 0.f, d = 0.f;
        #pragma unroll
        for (int k = 0; k < 32; k++){ a += r1[k][c]; d += r2[k][c]; }
        rcs[c] = a * (1.0f/Nn);
        ds[c]  = d * (1.0f/Nn);
    }
    __syncthreads();
    if (tid < Mm){
        int m = tid;
        float z = b0[m];
        #pragma unroll
        for (int cc = 0; cc < Cc; cc++)
            z += rcs[cc]*w0s[cc*Mm + m] + ds[cc]*w0s[(Cc+cc)*Mm + m];
        z0[m] = z;
    }
    __syncthreads();
    int t = tid >> 2, m = tid & 3;
    const float* S1r = &g_S1[(b*Nn + t)*Cc];
    const float* S2r = &g_S2[(b*Nn + t)*Cc];
    const float* Dr  = &g_D [(b*Nn + t)*Cc];
    float node = b1[m] + z0[m];
    #pragma unroll
    for (int cc = 0; cc < Cc; cc++)
        node += S1r[cc]*w1s[cc*Mm+m] + S2r[cc]*w1s[(Cc+cc)*Mm+m] + Dr[cc]*w1s[(2*Cc+cc)*Mm+m];
    g_p[(b*Nn + t)*Mm + m] = 1.0f / (1.0f + expf(-node));
}

// ---------------- sweep 2: V/U + rcs2/ds2 partial accumulation (atomics) ----------------
__global__ void k_sweep2(const float* __restrict__ x){
    int blk = blockIdx.x;
    bool is_v = blk < Bn*Nn;
    int bt = is_v ? blk : blk - Bn*Nn;
    int b = bt >> 8, t = bt & (Nn-1);
    const float* base;
    size_t stride;
    if (is_v){ base = x + (size_t)bt * Nn * Cc;              stride = Cc; }
    else     { base = x + (size_t)b*Nn*Nn*Cc + (size_t)t*Cc; stride = (size_t)Nn*Cc; }
    __shared__ float pv[Nn*Mm];
    __shared__ float red[8*Mm*32];
    int tid = threadIdx.x;
    ((float4*)pv)[tid] = ((const float4*)g_p)[b*Nn + tid];
    __syncthreads();
    int c = tid & 31, g = tid >> 5;
    float acc[Mm] = {0.f,0.f,0.f,0.f};
    #pragma unroll 8
    for (int j = g; j < Nn; j += 8){
        float v = base[(size_t)j*stride + c];
        #pragma unroll
        for (int m = 0; m < Mm; m++) acc[m] += v * pv[j*Mm + m];
    }
    #pragma unroll
    for (int m = 0; m < Mm; m++) red[(g*Mm + m)*32 + c] = acc[m];
    __syncthreads();
    if (g < Mm){
        int m = g;
        float s = 0.f;
        #pragma unroll
        for (int k = 0; k < 8; k++) s += red[(k*Mm + m)*32 + c];
        float val = s * (1.0f/Nn);
        if (is_v){
            g_V[(bt*Mm + m)*Cc + c] = val;
            float pt = pv[t*Mm + m];
            atomicAdd(&g_part1[(b*16 + (t >> 4))*128 + m*32 + c], pt * val);
        } else {
            g_U[(bt*Mm + m)*Cc + c] = val;
        }
    } else if (is_v){
        int m = g - 4;
        float pt = pv[t*Mm + m];
        float dv = g_D[bt*Cc + c];
        atomicAdd(&g_part2[(b*16 + (t >> 4))*128 + m*32 + c], pt * pt * dv);
    }
}

// ---------------- add[b,t,o]: 128 blocks, 8 t per block, 2 t per thread ----------------
// o1 transposed [384][8] so a thread's t-pair is one LDS.64 broadcast
#define ADD_SMEM (384*8*4 + 96*64*4)
__global__ void k_add(const float* __restrict__ w1d, const float* __restrict__ w0d,
                      const float* __restrict__ b0d, const float* __restrict__ b1d,
                      const float* __restrict__ b2d){
    extern __shared__ float ash[];
    float* o1  = ash;            // [384][8] transposed
    float* wsh = ash + 384*8;    // [96][64] chunk of w1d
    __shared__ float rsh[128], dsh[128], zred[256], z0sh[64];
    int b = blockIdx.x >> 5;
    int t0 = (blockIdx.x & 31) * 8;
    int tid = threadIdx.x;

    // fill o1 (transposed): 3072 elements
    #pragma unroll
    for (int it = 0; it < 12; it++){
        int idx = tid + it*256;
        int k = idx >> 3, tl = idx & 7;
        int t = t0 + tl;
        int seg = k >> 7, mc = k & 127;
        int m = mc >> 5, c = mc & 31;
        float pv = g_p[(b*Nn + t)*Mm + m];
        float val;
        if (seg == 0)      val = pv * g_U[((b*Nn + t)*Mm + m)*Cc + c];
        else if (seg == 1) val = pv * g_V[((b*Nn + t)*Mm + m)*Cc + c];
        else               val = pv * pv * g_D[(b*Nn + t)*Cc + c];
        o1[k*8 + tl] = val;
    }
    // z0 prologue from partials
    if (tid < 128){
        float a = 0.f, d = 0.f;
        #pragma unroll
        for (int s = 0; s < 16; s++){
            a += g_part1[(b*16 + s)*128 + tid];
            d += g_part2[(b*16 + s)*128 + tid];
        }
        rsh[tid] = a * (1.0f/Nn);
        dsh[tid] = d * (1.0f/Nn);
    }
    __syncthreads();
    {
        int o = tid & 63, q = tid >> 6;
        float s = 0.f;
        int k0 = q*32;
        #pragma unroll
        for (int k = k0; k < k0+32; k++)
            s += rsh[k]*w0d[k*OUTn + o] + dsh[k]*w0d[(128+k)*OUTn + o];
        zred[tid] = s;
    }
    __syncthreads();
    if (tid < 64)
        z0sh[tid] = zred[tid] + zred[tid+64] + zred[tid+128] + zred[tid+192]
                  + b0d[tid] + b1d[tid] + b2d[tid];

    int tg = tid >> 6, o = tid & 63;          // tg owns t-pair (tg*2, tg*2+1)
    float a0e = 0.f, a0o = 0.f, a1e = 0.f, a1o = 0.f;   // 2 acc per t (even/odd k)
    #pragma unroll
    for (int chunk = 0; chunk < 4; chunk++){
        __syncthreads();
        {   // stage 96 rows of w1d: 1536 float4
            const float4* w4 = (const float4*)(w1d + chunk*96*64);
            #pragma unroll
            for (int it = 0; it < 6; it++)
                ((float4*)wsh)[tid + it*256] = w4[tid + it*256];
        }
        __syncthreads();
        const float* ob = o1 + chunk*96*8 + tg*2;
        #pragma unroll 6
        for (int k = 0; k < 96; k += 2){
            float wv0 = wsh[(k    )*64 + o];
            float wv1 = wsh[(k + 1)*64 + o];
            float2 t0v = *(const float2*)(ob + (k    )*8);
            float2 t1v = *(const float2*)(ob + (k + 1)*8);
            a0e += t0v.x * wv0;  a1e += t0v.y * wv0;
            a0o += t1v.x * wv1;  a1o += t1v.y * wv1;
        }
    }
    float z = z0sh[o];
    g_add[(b*Nn + t0 + tg*2    )*OUTn + o] = (a0e + a0o) + z;
    g_add[(b*Nn + t0 + tg*2 + 1)*OUTn + o] = (a1e + a1o) + z;
}

// ---------------- main fused GEMM: JPB 4, ldmatrix fragment loads ----------------
__device__ __forceinline__ void mma16816(float* c, const uint32_t* a, uint32_t b0, uint32_t b1){
    asm volatile("mma.sync.aligned.m16n8k16.row.col.f32.f16.f16.f32 "
        "{%0,%1,%2,%3}, {%4,%5,%6,%7}, {%8,%9}, {%0,%1,%2,%3};\n"
        : "+f"(c[0]), "+f"(c[1]), "+f"(c[2]), "+f"(c[3])
        : "r"(a[0]), "r"(a[1]), "r"(a[2]), "r"(a[3]), "r"(b0), "r"(b1));
}
__device__ __forceinline__ void ldsm_x4(uint32_t& r0, uint32_t& r1, uint32_t& r2, uint32_t& r3, uint32_t addr){
    asm volatile("ldmatrix.sync.aligned.m8n8.x4.shared.b16 {%0,%1,%2,%3}, [%4];"
        : "=r"(r0), "=r"(r1), "=r"(r2), "=r"(r3) : "r"(addr));
}
__device__ __forceinline__ uint32_t smem_u32(const void* p){
    uint32_t a;
    asm("{ .reg .u64 t; cvta.to.shared.u64 t, %1; cvt.u32.u64 %0, t; }" : "=r"(a) : "l"(p));
    return a;
}

#define AS 264
#define ASB (AS*2)
#define SMEM_MAIN (128*AS*2 + 64*AS*2 + 512*4 + 64*4)
#define JPB 4

__global__ __launch_bounds__(256, 2) void k_main(const float* __restrict__ x, float* __restrict__ out){
    extern __shared__ __align__(16) char smem[];
    __half* Ash  = (__half*)smem;
    __half* Wsh  = Ash + 128*AS;
    float*  sshf = (float*)(Wsh + 64*AS);
    float*  addsh = sshf + 512;

    int blk = blockIdx.x;
    int ib = blk & 1, jp = (blk >> 1) & 63, b = blk >> 7;
    int i0 = ib * 128;
    int tid = threadIdx.x;

    {
        const uint4* Wt4 = (const uint4*)g_Wt;
        #pragma unroll
        for (int it = 0; it < 8; it++){
            int idx = tid + it*256;
            int o = idx >> 5, kq = idx & 31;
            *(uint4*)&Wsh[o*AS + kq*8] = Wt4[idx];
        }
    }
    if (tid < 128)
        ((float4*)sshf)[tid] = ((const float4*)g_p)[b*Nn + i0 + tid];
    __syncthreads();

    int lane = tid & 31, wid = tid >> 5;
    int wr = wid >> 1, wc = wid & 1;
    int gid = lane >> 2, tg = lane & 3;

    uint32_t ash_u = smem_u32(Ash);
    uint32_t wsh_u = smem_u32(Wsh);
    int lrow = lane & 15, lsel = lane >> 4;
    uint32_t aAddr0 = ash_u + (uint32_t)(wr*32 + lrow)*ASB + (uint32_t)lsel*16;
    uint32_t bAddr0 = wsh_u + (uint32_t)(wc*32 + lrow)*ASB + (uint32_t)lsel*16;

    float2 vc[8];
    float4 pjv;
    float  addv;
    {
        int j = jp*JPB;
        size_t base_c = (((size_t)(b*Nn) + i0)*Nn + j)*Cc;
        #pragma unroll
        for (int it = 0; it < 8; it++){
            int idx = tid + it*256;
            int i = idx >> 4, cp = idx & 15;
            vc[it] = *(const float2*)(x + base_c + (size_t)i*(Nn*Cc) + cp*2);
        }
        pjv  = ((const float4*)g_p)[b*Nn + j];
        addv = g_add[(b*Nn + j)*OUTn + (tid & 63)];
    }

    for (int jj = 0; jj < JPB; jj++){
        int j = jp*JPB + jj;
        if (jj > 0) __syncthreads();

        {
            size_t base_r = (((size_t)(b*Nn) + j)*Nn + i0)*Cc;
            #pragma unroll
            for (int it = 0; it < 8; it++){
                int idx = tid + it*256;
                int i = idx >> 4, cp = idx & 15;
                float4 pi = ((const float4*)sshf)[i];
                float4 s = make_float4(pi.x*pjv.x, pi.y*pjv.y, pi.z*pjv.z, pi.w*pjv.w);
                float2 v = vc[it];
                __half* arow = Ash + i*AS + cp*2;
                *(half2*)(arow     ) = __floats2half2_rn(s.x*v.x, s.x*v.y);
                *(half2*)(arow + 32) = __floats2half2_rn(s.y*v.x, s.y*v.y);
                *(half2*)(arow + 64) = __floats2half2_rn(s.z*v.x, s.z*v.y);
                *(half2*)(arow + 96) = __floats2half2_rn(s.w*v.x, s.w*v.y);
                float2 w = *(const float2*)(x + base_r + (size_t)i*Cc + cp*2);
                __half* brow = arow + 128;
                *(half2*)(brow     ) = __floats2half2_rn(s.x*w.x, s.x*w.y);
                *(half2*)(brow + 32) = __floats2half2_rn(s.y*w.x, s.y*w.y);
                *(half2*)(brow + 64) = __floats2half2_rn(s.z*w.x, s.z*w.y);
                *(half2*)(brow + 96) = __floats2half2_rn(s.w*w.x, s.w*w.y);
            }
            if (tid < 64) addsh[tid] = addv;
        }
        __syncthreads();

        if (jj + 1 < JPB){
            int j2 = j + 1;
            size_t base_c = (((size_t)(b*Nn) + i0)*Nn + j2)*Cc;
            #pragma unroll
            for (int it = 0; it < 8; it++){
                int idx = tid + it*256;
                int i = idx >> 4, cp = idx & 15;
                vc[it] = *(const float2*)(x + base_c + (size_t)i*(Nn*Cc) + cp*2);
            }
            pjv  = ((const float4*)g_p)[b*Nn + j2];
            addv = g_add[(b*Nn + j2)*OUTn + (tid & 63)];
        }

        float acc[2][4][4];
        #pragma unroll
        for (int rt = 0; rt < 2; rt++)
            #pragma unroll
            for (int nt = 0; nt < 4; nt++)
                #pragma unroll
                for (int q = 0; q < 4; q++) acc[rt][nt][q] = 0.f;

        #pragma unroll
        for (int kk = 0; kk < 16; kk++){
            uint32_t kb = (uint32_t)(kk*16*2);
            uint32_t a[2][4];
            ldsm_x4(a[0][0], a[0][1], a[0][2], a[0][3], aAddr0 + kb);
            ldsm_x4(a[1][0], a[1][1], a[1][2], a[1][3], aAddr0 + kb + 16*ASB);
            uint32_t b00, b01, b10, b11, b20, b21, b30, b31;
            ldsm_x4(b00, b10, b01, b11, bAddr0 + kb);
            ldsm_x4(b20, b30, b21, b31, bAddr0 + kb + 16*ASB);
            mma16816(acc[0][0], a[0], b00, b01);
            mma16816(acc[1][0], a[1], b00, b01);
            mma16816(acc[0][1], a[0], b10, b11);
            mma16816(acc[1][1], a[1], b10, b11);
            mma16816(acc[0][2], a[0], b20, b21);
            mma16816(acc[1][2], a[1], b20, b21);
            mma16816(acc[0][3], a[0], b30, b31);
            mma16816(acc[1][3], a[1], b30, b31);
        }

        #pragma unroll
        for (int rt = 0; rt < 2; rt++){
            int r = i0 + wr*32 + rt*16 + gid;
            #pragma unroll
            for (int nt = 0; nt < 4; nt++){
                int o = wc*32 + nt*8 + tg*2;
                float2 ad = *(const float2*)&addsh[o];
                size_t base = (((size_t)(b*Nn) + r)*Nn + j)*OUTn + o;
                float2 v0 = make_float2(acc[rt][nt][0] + ad.x, acc[rt][nt][1] + ad.y);
                float2 v1 = make_float2(acc[rt][nt][2] + ad.x, acc[rt][nt][3] + ad.y);
                *(float2*)(out + base) = v0;
                *(float2*)(out + base + (size_t)8*Nn*OUTn) = v1;
            }
        }
    }
}

// ---------------- launch ----------------
extern "C" void kernel_launch(void* const* d_in, const int* in_sizes, int n_in,
                              void* d_out, int out_size) {
    const float* x    = (const float*)d_in[0];
    const float* w1nb = (const float*)d_in[1];
    const float* b1nb = (const float*)d_in[2];
    const float* w0nb = (const float*)d_in[3];
    const float* b0nb = (const float*)d_in[4];
    const float* w2d  = (const float*)d_in[5];
    const float* b2d  = (const float*)d_in[6];
    const float* w1d  = (const float*)d_in[7];
    const float* b1d  = (const float*)d_in[8];
    const float* w0d  = (const float*)d_in[9];
    const float* b0d  = (const float*)d_in[10];
    float* out = (float*)d_out;

    cudaFuncSetAttribute(k_main, cudaFuncAttributeMaxDynamicSharedMemorySize, SMEM_MAIN);
    cudaFuncSetAttribute(k_add, cudaFuncAttributeMaxDynamicSharedMemorySize, ADD_SMEM);

    k_sweep1<<<2*Bn*Nn + 64 + 16, 256>>>(x, w2d);   // +16 blocks zero the partials
    k_neighb<<<Bn, 1024>>>(w1nb, b1nb, w0nb, b0nb);
    k_sweep2<<<2*Bn*Nn, 256>>>(x);
    k_add<<<Bn*32, 256, ADD_SMEM>>>(w1d, w0d, b0d, b1d, b2d);
    k_main<<<Bn*Nn*2/JPB, 256, SMEM_MAIN>>>(x, out);
}

// round 17
// speedup vs baseline: 1.0469x; 1.0197x over previous
#include <cuda_runtime.h>
#include <cuda_fp16.h>
#include <cstdint>

#define Bn 4
#define Nn 256
#define Cc 32
#define Mm 4
#define OUTn 64

// ---------------- scratch (device globals: no allocation allowed) ----------------
__device__ float g_S1[Bn*Nn*Cc];      // rowsum  (mean over axis1)
__device__ float g_S2[Bn*Nn*Cc];      // colsum  (mean over axis2)
__device__ float g_D [Bn*Nn*Cc];      // diag
__device__ float g_p [Bn*Nn*Mm];      // sigmoid neighborhood
__device__ float g_U [Bn*Nn*Mm*Cc];
__device__ float g_V [Bn*Nn*Mm*Cc];
__device__ float g_part1[Bn*16*128];  // rcs2 partials (atomic accum)
__device__ float g_part2[Bn*16*128];  // ds2  partials (atomic accum)
__device__ float g_add[Bn*Nn*OUTn];
__device__ __half g_Wt[OUTn*2*Mm*Cc]; // w2d transposed: Wt[o][k]

// ---------------- sweep 1: rowpass (S2, D) + colpass (S1) + w2d->half + zero partials ----------------
__global__ void k_sweep1(const float* __restrict__ x, const float* __restrict__ w2d){
    int blk = blockIdx.x;
    int tid = threadIdx.x;
    if (blk >= 2*Bn*Nn + 64){
        int idx = (blk - (2*Bn*Nn + 64)) * 256 + tid;   // < 4096
        float4 z = make_float4(0.f, 0.f, 0.f, 0.f);
        if (idx < 2048) ((float4*)g_part1)[idx] = z;
        else            ((float4*)g_part2)[idx - 2048] = z;
        return;
    }
    if (blk >= 2*Bn*Nn){
        int idx = (blk - 2*Bn*Nn) * 256 + tid;   // 16384
        int o = idx >> 8, k = idx & 255;
        g_Wt[idx] = __float2half(w2d[k*OUTn + o]);
        return;
    }
    __shared__ float red[8][32];
    int c = tid & 31, g = tid >> 5;
    if (blk < Bn*Nn){
        int bt = blk;
        int t = bt & (Nn-1);
        const float* xrow = x + (size_t)bt * Nn * Cc;
        float s = 0.f;
        #pragma unroll 8
        for (int j = g; j < Nn; j += 8) s += xrow[j*Cc + c];
        red[g][c] = s;
        __syncthreads();
        if (g == 0){
            float tot = 0.f;
            #pragma unroll
            for (int k = 0; k < 8; k++) tot += red[k][c];
            g_S2[bt*Cc + c] = tot * (1.0f/Nn);
            g_D [bt*Cc + c] = xrow[t*Cc + c];
        }
    } else {
        int bt = blk - Bn*Nn;
        int b = bt >> 8, t = bt & (Nn-1);
        const float* xb = x + (size_t)b*Nn*Nn*Cc + (size_t)t*Cc;
        float s = 0.f;
        #pragma unroll 8
        for (int i = g; i < Nn; i += 8) s += xb[(size_t)i*Nn*Cc + c];
        red[g][c] = s;
        __syncthreads();
        if (g == 0){
            float tot = 0.f;
            #pragma unroll
            for (int k = 0; k < 8; k++) tot += red[k][c];
            g_S1[bt*Cc + c] = tot * (1.0f/Nn);
        }
    }
}

// ---------------- neighborhood sigmoid: p[b,t,m], 1024 threads ----------------
__global__ __launch_bounds__(1024) void k_neighb(const float* __restrict__ w1, const float* __restrict__ b1,
                         const float* __restrict__ w0, const float* __restrict__ b0){
    int b = blockIdx.x;
    __shared__ float w1s[3*Cc*Mm];
    __shared__ float w0s[2*Cc*Mm];
    __shared__ float rcs[Cc], ds[Cc], z0[Mm];
    __shared__ float r1[32][32], r2[32][32];
    int tid = threadIdx.x;
    if (tid < 3*Cc*Mm) w1s[tid] = w1[tid];
    if (tid < 2*Cc*Mm) w0s[tid] = w0[tid];
    int c = tid & 31, g = tid >> 5;
    float s1 = 0.f, s2 = 0.f;
    #pragma unroll
    for (int t = g; t < Nn; t += 32){
        s1 += g_S1[(b*Nn + t)*Cc + c];
        s2 += g_D [(b*Nn + t)*Cc + c];
    }
    r1[g][c] = s1; r2[g][c] = s2;
    __syncthreads();
    if (tid < 32){
        float a = 0.f, d = 0.f;
        #pragma unroll
        for (int k = 0; k < 32; k++){ a += r1[k][c]; d += r2[k][c]; }
        rcs[c] = a * (1.0f/Nn);
        ds[c]  = d * (1.0f/Nn);
    }
    __syncthreads();
    if (tid < Mm){
        int m = tid;
        float z = b0[m];
        #pragma unroll
        for (int cc = 0; cc < Cc; cc++)
            z += rcs[cc]*w0s[cc*Mm + m] + ds[cc]*w0s[(Cc+cc)*Mm + m];
        z0[m] = z;
    }
    __syncthreads();
    int t = tid >> 2, m = tid & 3;
    const float* S1r = &g_S1[(b*Nn + t)*Cc];
    const float* S2r = &g_S2[(b*Nn + t)*Cc];
    const float* Dr  = &g_D [(b*Nn + t)*Cc];
    float node = b1[m] + z0[m];
    #pragma unroll
    for (int cc = 0; cc < Cc; cc++)
        node += S1r[cc]*w1s[cc*Mm+m] + S2r[cc]*w1s[(Cc+cc)*Mm+m] + Dr[cc]*w1s[(2*Cc+cc)*Mm+m];
    g_p[(b*Nn + t)*Mm + m] = 1.0f / (1.0f + expf(-node));
}

// ---------------- sweep 2: V/U + rcs2/ds2 partial accumulation (atomics) ----------------
__global__ void k_sweep2(const float* __restrict__ x){
    int blk = blockIdx.x;
    bool is_v = blk < Bn*Nn;
    int bt = is_v ? blk : blk - Bn*Nn;
    int b = bt >> 8, t = bt & (Nn-1);
    const float* base;
    size_t stride;
    if (is_v){ base = x + (size_t)bt * Nn * Cc;              stride = Cc; }
    else     { base = x + (size_t)b*Nn*Nn*Cc + (size_t)t*Cc; stride = (size_t)Nn*Cc; }
    __shared__ float pv[Nn*Mm];
    __shared__ float red[8*Mm*32];
    int tid = threadIdx.x;
    ((float4*)pv)[tid] = ((const float4*)g_p)[b*Nn + tid];
    __syncthreads();
    int c = tid & 31, g = tid >> 5;
    float acc[Mm] = {0.f,0.f,0.f,0.f};
    #pragma unroll 8
    for (int j = g; j < Nn; j += 8){
        float v = base[(size_t)j*stride + c];
        #pragma unroll
        for (int m = 0; m < Mm; m++) acc[m] += v * pv[j*Mm + m];
    }
    #pragma unroll
    for (int m = 0; m < Mm; m++) red[(g*Mm + m)*32 + c] = acc[m];
    __syncthreads();
    if (g < Mm){
        int m = g;
        float s = 0.f;
        #pragma unroll
        for (int k = 0; k < 8; k++) s += red[(k*Mm + m)*32 + c];
        float val = s * (1.0f/Nn);
        if (is_v){
            g_V[(bt*Mm + m)*Cc + c] = val;
            float pt = pv[t*Mm + m];
            atomicAdd(&g_part1[(b*16 + (t >> 4))*128 + m*32 + c], pt * val);
        } else {
            g_U[(bt*Mm + m)*Cc + c] = val;
        }
    } else if (is_v){
        int m = g - 4;
        float pt = pv[t*Mm + m];
        float dv = g_D[bt*Cc + c];
        atomicAdd(&g_part2[(b*16 + (t >> 4))*128 + m*32 + c], pt * pt * dv);
    }
}

// ---------------- add[b,t,o]: 128 blocks, 8 t per block, 2 t per thread ----------------
// Full w1d (384x64 = 98KB) staged once; one uninterrupted 384-k loop.
#define ADD_SMEM (384*8*4 + 384*64*4)
__global__ void k_add(const float* __restrict__ w1d, const float* __restrict__ w0d,
                      const float* __restrict__ b0d, const float* __restrict__ b1d,
                      const float* __restrict__ b2d){
    extern __shared__ float ash[];
    float* o1  = ash;            // [384][8] transposed
    float* wsh = ash + 384*8;    // [384][64] full w1d
    __shared__ float rsh[128], dsh[128], zred[256], z0sh[64];
    int b = blockIdx.x >> 5;
    int t0 = (blockIdx.x & 31) * 8;
    int tid = threadIdx.x;

    // stage ALL of w1d: 6144 float4 (24 per thread, high MLP)
    {
        const float4* w4 = (const float4*)w1d;
        #pragma unroll
        for (int it = 0; it < 24; it++)
            ((float4*)wsh)[tid + it*256] = w4[tid + it*256];
    }
    // fill o1 (transposed): 3072 elements
    #pragma unroll
    for (int it = 0; it < 12; it++){
        int idx = tid + it*256;
        int k = idx >> 3, tl = idx & 7;
        int t = t0 + tl;
        int seg = k >> 7, mc = k & 127;
        int m = mc >> 5, c = mc & 31;
        float pv = g_p[(b*Nn + t)*Mm + m];
        float val;
        if (seg == 0)      val = pv * g_U[((b*Nn + t)*Mm + m)*Cc + c];
        else if (seg == 1) val = pv * g_V[((b*Nn + t)*Mm + m)*Cc + c];
        else               val = pv * pv * g_D[(b*Nn + t)*Cc + c];
        o1[k*8 + tl] = val;
    }
    // z0 prologue from partials
    if (tid < 128){
        float a = 0.f, d = 0.f;
        #pragma unroll
        for (int s = 0; s < 16; s++){
            a += g_part1[(b*16 + s)*128 + tid];
            d += g_part2[(b*16 + s)*128 + tid];
        }
        rsh[tid] = a * (1.0f/Nn);
        dsh[tid] = d * (1.0f/Nn);
    }
    __syncthreads();
    {
        int o = tid & 63, q = tid >> 6;
        float s = 0.f;
        int k0 = q*32;
        #pragma unroll
        for (int k = k0; k < k0+32; k++)
            s += rsh[k]*w0d[k*OUTn + o] + dsh[k]*w0d[(128+k)*OUTn + o];
        zred[tid] = s;
    }
    __syncthreads();
    if (tid < 64)
        z0sh[tid] = zred[tid] + zred[tid+64] + zred[tid+128] + zred[tid+192]
                  + b0d[tid] + b1d[tid] + b2d[tid];
    __syncthreads();

    int tg = tid >> 6, o = tid & 63;          // tg owns t-pair (tg*2, tg*2+1)
    float a0e = 0.f, a0o = 0.f, a1e = 0.f, a1o = 0.f;   // 2 acc per t (even/odd k)
    const float* ob = o1 + tg*2;
    #pragma unroll 8
    for (int k = 0; k < 384; k += 2){
        float wv0 = wsh[(k    )*64 + o];
        float wv1 = wsh[(k + 1)*64 + o];
        float2 t0v = *(const float2*)(ob + (k    )*8);
        float2 t1v = *(const float2*)(ob + (k + 1)*8);
        a0e += t0v.x * wv0;  a1e += t0v.y * wv0;
        a0o += t1v.x * wv1;  a1o += t1v.y * wv1;
    }
    float z = z0sh[o];
    g_add[(b*Nn + t0 + tg*2    )*OUTn + o] = (a0e + a0o) + z;
    g_add[(b*Nn + t0 + tg*2 + 1)*OUTn + o] = (a1e + a1o) + z;
}

// ---------------- main fused GEMM: JPB 4, ldmatrix fragment loads ----------------
__device__ __forceinline__ void mma16816(float* c, const uint32_t* a, uint32_t b0, uint32_t b1){
    asm volatile("mma.sync.aligned.m16n8k16.row.col.f32.f16.f16.f32 "
        "{%0,%1,%2,%3}, {%4,%5,%6,%7}, {%8,%9}, {%0,%1,%2,%3};\n"
        : "+f"(c[0]), "+f"(c[1]), "+f"(c[2]), "+f"(c[3])
        : "r"(a[0]), "r"(a[1]), "r"(a[2]), "r"(a[3]), "r"(b0), "r"(b1));
}
__device__ __forceinline__ void ldsm_x4(uint32_t& r0, uint32_t& r1, uint32_t& r2, uint32_t& r3, uint32_t addr){
    asm volatile("ldmatrix.sync.aligned.m8n8.x4.shared.b16 {%0,%1,%2,%3}, [%4];"
        : "=r"(r0), "=r"(r1), "=r"(r2), "=r"(r3) : "r"(addr));
}
__device__ __forceinline__ uint32_t smem_u32(const void* p){
    uint32_t a;
    asm("{ .reg .u64 t; cvta.to.shared.u64 t, %1; cvt.u32.u64 %0, t; }" : "=r"(a) : "l"(p));
    return a;
}

#define AS 264
#define ASB (AS*2)
#define SMEM_MAIN (128*AS*2 + 64*AS*2 + 512*4 + 64*4)
#define JPB 4

__global__ __launch_bounds__(256, 2) void k_main(const float* __restrict__ x, float* __restrict__ out){
    extern __shared__ __align__(16) char smem[];
    __half* Ash  = (__half*)smem;
    __half* Wsh  = Ash + 128*AS;
    float*  sshf = (float*)(Wsh + 64*AS);
    float*  addsh = sshf + 512;

    int blk = blockIdx.x;
    int ib = blk & 1, jp = (blk >> 1) & 63, b = blk >> 7;
    int i0 = ib * 128;
    int tid = threadIdx.x;

    {
        const uint4* Wt4 = (const uint4*)g_Wt;
        #pragma unroll
        for (int it = 0; it < 8; it++){
            int idx = tid + it*256;
            int o = idx >> 5, kq = idx & 31;
            *(uint4*)&Wsh[o*AS + kq*8] = Wt4[idx];
        }
    }
    if (tid < 128)
        ((float4*)sshf)[tid] = ((const float4*)g_p)[b*Nn + i0 + tid];
    __syncthreads();

    int lane = tid & 31, wid = tid >> 5;
    int wr = wid >> 1, wc = wid & 1;
    int gid = lane >> 2, tg = lane & 3;

    uint32_t ash_u = smem_u32(Ash);
    uint32_t wsh_u = smem_u32(Wsh);
    int lrow = lane & 15, lsel = lane >> 4;
    uint32_t aAddr0 = ash_u + (uint32_t)(wr*32 + lrow)*ASB + (uint32_t)lsel*16;
    uint32_t bAddr0 = wsh_u + (uint32_t)(wc*32 + lrow)*ASB + (uint32_t)lsel*16;

    float2 vc[8];
    float4 pjv;
    float  addv;
    {
        int j = jp*JPB;
        size_t base_c = (((size_t)(b*Nn) + i0)*Nn + j)*Cc;
        #pragma unroll
        for (int it = 0; it < 8; it++){
            int idx = tid + it*256;
            int i = idx >> 4, cp = idx & 15;
            vc[it] = *(const float2*)(x + base_c + (size_t)i*(Nn*Cc) + cp*2);
        }
        pjv  = ((const float4*)g_p)[b*Nn + j];
        addv = g_add[(b*Nn + j)*OUTn + (tid & 63)];
    }

    for (int jj = 0; jj < JPB; jj++){
        int j = jp*JPB + jj;
        if (jj > 0) __syncthreads();

        {
            size_t base_r = (((size_t)(b*Nn) + j)*Nn + i0)*Cc;
            #pragma unroll
            for (int it = 0; it < 8; it++){
                int idx = tid + it*256;
                int i = idx >> 4, cp = idx & 15;
                float4 pi = ((const float4*)sshf)[i];
                float4 s = make_float4(pi.x*pjv.x, pi.y*pjv.y, pi.z*pjv.z, pi.w*pjv.w);
                float2 v = vc[it];
                __half* arow = Ash + i*AS + cp*2;
                *(half2*)(arow     ) = __floats2half2_rn(s.x*v.x, s.x*v.y);
                *(half2*)(arow + 32) = __floats2half2_rn(s.y*v.x, s.y*v.y);
                *(half2*)(arow + 64) = __floats2half2_rn(s.z*v.x, s.z*v.y);
                *(half2*)(arow + 96) = __floats2half2_rn(s.w*v.x, s.w*v.y);
                float2 w = *(const float2*)(x + base_r + (size_t)i*Cc + cp*2);
                __half* brow = arow + 128;
                *(half2*)(brow     ) = __floats2half2_rn(s.x*w.x, s.x*w.y);
                *(half2*)(brow + 32) = __floats2half2_rn(s.y*w.x, s.y*w.y);
                *(half2*)(brow + 64) = __floats2half2_rn(s.z*w.x, s.z*w.y);
                *(half2*)(brow + 96) = __floats2half2_rn(s.w*w.x, s.w*w.y);
            }
            if (tid < 64) addsh[tid] = addv;
        }
        __syncthreads();

        if (jj + 1 < JPB){
            int j2 = j + 1;
            size_t base_c = (((size_t)(b*Nn) + i0)*Nn + j2)*Cc;
            #pragma unroll
            for (int it = 0; it < 8; it++){
                int idx = tid + it*256;
                int i = idx >> 4, cp = idx & 15;
                vc[it] = *(const float2*)(x + base_c + (size_t)i*(Nn*Cc) + cp*2);
            }
            pjv  = ((const float4*)g_p)[b*Nn + j2];
            addv = g_add[(b*Nn + j2)*OUTn + (tid & 63)];
        }

        float acc[2][4][4];
        #pragma unroll
        for (int rt = 0; rt < 2; rt++)
            #pragma unroll
            for (int nt = 0; nt < 4; nt++)
                #pragma unroll
                for (int q = 0; q < 4; q++) acc[rt][nt][q] = 0.f;

        #pragma unroll
        for (int kk = 0; kk < 16; kk++){
            uint32_t kb = (uint32_t)(kk*16*2);
            uint32_t a[2][4];
            ldsm_x4(a[0][0], a[0][1], a[0][2], a[0][3], aAddr0 + kb);
            ldsm_x4(a[1][0], a[1][1], a[1][2], a[1][3], aAddr0 + kb + 16*ASB);
            uint32_t b00, b01, b10, b11, b20, b21, b30, b31;
            ldsm_x4(b00, b10, b01, b11, bAddr0 + kb);
            ldsm_x4(b20, b30, b21, b31, bAddr0 + kb + 16*ASB);
            mma16816(acc[0][0], a[0], b00, b01);
            mma16816(acc[1][0], a[1], b00, b01);
            mma16816(acc[0][1], a[0], b10, b11);
            mma16816(acc[1][1], a[1], b10, b11);
            mma16816(acc[0][2], a[0], b20, b21);
            mma16816(acc[1][2], a[1], b20, b21);
            mma16816(acc[0][3], a[0], b30, b31);
            mma16816(acc[1][3], a[1], b30, b31);
        }

        #pragma unroll
        for (int rt = 0; rt < 2; rt++){
            int r = i0 + wr*32 + rt*16 + gid;
            #pragma unroll
            for (int nt = 0; nt < 4; nt++){
                int o = wc*32 + nt*8 + tg*2;
                float2 ad = *(const float2*)&addsh[o];
                size_t base = (((size_t)(b*Nn) + r)*Nn + j)*OUTn + o;
                float2 v0 = make_float2(acc[rt][nt][0] + ad.x, acc[rt][nt][1] + ad.y);
                float2 v1 = make_float2(acc[rt][nt][2] + ad.x, acc[rt][nt][3] + ad.y);
                *(float2*)(out + base) = v0;
                *(float2*)(out + base + (size_t)8*Nn*OUTn) = v1;
            }
        }
    }
}

// ---------------- launch ----------------
extern "C" void kernel_launch(void* const* d_in, const int* in_sizes, int n_in,
                              void* d_out, int out_size) {
    const float* x    = (const float*)d_in[0];
    const float* w1nb = (const float*)d_in[1];
    const float* b1nb = (const float*)d_in[2];
    const float* w0nb = (const float*)d_in[3];
    const float* b0nb = (const float*)d_in[4];
    const float* w2d  = (const float*)d_in[5];
    const float* b2d  = (const float*)d_in[6];
    const float* w1d  = (const float*)d_in[7];
    const float* b1d  = (const float*)d_in[8];
    const float* w0d  = (const float*)d_in[9];
    const float* b0d  = (const float*)d_in[10];
    float* out = (float*)d_out;

    cudaFuncSetAttribute(k_main, cudaFuncAttributeMaxDynamicSharedMemorySize, SMEM_MAIN);
    cudaFuncSetAttribute(k_add, cudaFuncAttributeMaxDynamicSharedMemorySize, ADD_SMEM);

    k_sweep1<<<2*Bn*Nn + 64 + 16, 256>>>(x, w2d);   // +16 blocks zero the partials
    k_neighb<<<Bn, 1024>>>(w1nb, b1nb, w0nb, b0nb);
    k_sweep2<<<2*Bn*Nn, 256>>>(x);
    k_add<<<Bn*32, 256, ADD_SMEM>>>(w1d, w0d, b0d, b1d, b2d);
    k_main<<<Bn*Nn*2/JPB, 256, SMEM_MAIN>>>(x, out);
}